// round 2
// baseline (speedup 1.0000x reference)
#include <cuda_runtime.h>
#include <math.h>

#define B_    32
#define TENC  200
#define E_    512
#define D_    1024
#define P_    256
#define M_    80
#define TDEC  600
#define A_    128
#define LF_   32
#define KW_   31
#define PADW  15
#define NBLK  128
#define NTHR  256

// ---------------- device scratch (static, allocation-free) ----------------
__device__ float g_pre[(size_t)B_ * TDEC * P_];      // prenet out [b][t][256]
__device__ float g_pm[(size_t)B_ * TENC * A_];       // enc @ Wm^T [b][i][128]
__device__ float g_hatt[B_ * D_];
__device__ float g_catt[B_ * D_];
__device__ float g_hgen[B_ * D_];
__device__ float g_cgen[B_ * D_];
__device__ float g_ctx[2][B_ * E_];                  // ping-pong context
__device__ float g_wprev[B_ * TENC];
__device__ float g_wcum[B_ * TENC];
__device__ float g_gatt[(size_t)4 * D_ * B_];        // att gate preacts [row][b]
__device__ float g_ggen[(size_t)4 * D_ * B_];        // gen gate preacts [row][b]

// ---------------- grid barrier ----------------
__device__ unsigned g_count = 0;
__device__ volatile unsigned g_sense = 0;

__device__ __forceinline__ void grid_bar(unsigned& ls) {
    __syncthreads();
    ls ^= 1u;
    if (threadIdx.x == 0) {
        __threadfence();
        unsigned old = atomicAdd(&g_count, 1u);
        if (old == NBLK - 1) {
            atomicExch(&g_count, 0u);
            __threadfence();
            g_sense = ls;                 // volatile release
        } else {
            while (g_sense != ls) { __nanosleep(128); }
            __threadfence();
        }
    }
    __syncthreads();
}

// ---------------- helpers ----------------
__device__ __forceinline__ float warp_sum(float v) {
    v += __shfl_xor_sync(0xffffffffu, v, 16);
    v += __shfl_xor_sync(0xffffffffu, v, 8);
    v += __shfl_xor_sync(0xffffffffu, v, 4);
    v += __shfl_xor_sync(0xffffffffu, v, 2);
    v += __shfl_xor_sync(0xffffffffu, v, 1);
    return v;
}
__device__ __forceinline__ float warp_max(float v) {
    v = fmaxf(v, __shfl_xor_sync(0xffffffffu, v, 16));
    v = fmaxf(v, __shfl_xor_sync(0xffffffffu, v, 8));
    v = fmaxf(v, __shfl_xor_sync(0xffffffffu, v, 4));
    v = fmaxf(v, __shfl_xor_sync(0xffffffffu, v, 2));
    v = fmaxf(v, __shfl_xor_sync(0xffffffffu, v, 1));
    return v;
}
__device__ __forceinline__ float sigf(float x) { return 1.f / (1.f + __expf(-x)); }

// ---------------- LSTM gate GEMM: gates[4096 rows][32 b] ----------------
// Block handles 32 rows (rows = blk*32..+32), all 32 b.
// Thread tile 4 rows x 4 b, K split in 4 groups, smem-staged tiles (pad 65).
__device__ void lstm_gates(const float* __restrict__ Wih, const float* __restrict__ Whh,
                           int KX,
                           const float* s0, int l0, int st0,
                           const float* s1, int l1, int st1,
                           const float* s2, int st2,
                           float* __restrict__ gates_out, float* pool, int blk) {
    const int KTOT = KX + D_;
    const int rowbase = blk * 32;
    const int tid = threadIdx.x;
    const int kg = tid >> 6;            // 0..3
    const int rg = (tid >> 3) & 7;      // 0..7
    const int bg = tid & 7;             // 0..7
    const int lrow = tid >> 3;          // 0..31 (staging row / b)
    const int kof8 = (tid & 7) * 8;

    float* w_s = pool;                  // 32*65 = 2080
    float* x_s = pool + 2080;           // 2080
    float* red = pool + 4160;           // 4*32*33 = 4224

    float acc[4][4];
    #pragma unroll
    for (int i = 0; i < 4; i++)
        #pragma unroll
        for (int j = 0; j < 4; j++) acc[i][j] = 0.f;

    for (int tb = 0; tb < KTOT; tb += 64) {
        // stage W tile
        {
            int k = tb + kof8;
            const float* src = (k < KX)
                ? Wih + (size_t)(rowbase + lrow) * KX + k
                : Whh + (size_t)(rowbase + lrow) * D_ + (k - KX);
            float4 a = *(const float4*)src;
            float4 b4 = *(const float4*)(src + 4);
            float* d = w_s + lrow * 65 + kof8;
            d[0] = a.x; d[1] = a.y; d[2] = a.z; d[3] = a.w;
            d[4] = b4.x; d[5] = b4.y; d[6] = b4.z; d[7] = b4.w;
        }
        // stage x tile (b = lrow)
        {
            int k = tb + kof8;
            const float* src;
            if (k < l0)            src = s0 + (size_t)lrow * st0 + k;
            else if (k < l0 + l1)  src = s1 + (size_t)lrow * st1 + (k - l0);
            else                   src = s2 + (size_t)lrow * st2 + (k - l0 - l1);
            float4 a = *(const float4*)src;
            float4 b4 = *(const float4*)(src + 4);
            float* d = x_s + lrow * 65 + kof8;
            d[0] = a.x; d[1] = a.y; d[2] = a.z; d[3] = a.w;
            d[4] = b4.x; d[5] = b4.y; d[6] = b4.z; d[7] = b4.w;
        }
        __syncthreads();
        const float* wp = w_s + (4 * rg) * 65 + kg * 16;
        const float* xp = x_s + (4 * bg) * 65 + kg * 16;
        #pragma unroll
        for (int kk = 0; kk < 16; kk++) {
            float w0 = wp[kk], w1 = wp[kk + 65], w2 = wp[kk + 130], w3 = wp[kk + 195];
            float x0 = xp[kk], x1 = xp[kk + 65], x2 = xp[kk + 130], x3 = xp[kk + 195];
            acc[0][0] += w0 * x0; acc[0][1] += w0 * x1; acc[0][2] += w0 * x2; acc[0][3] += w0 * x3;
            acc[1][0] += w1 * x0; acc[1][1] += w1 * x1; acc[1][2] += w1 * x2; acc[1][3] += w1 * x3;
            acc[2][0] += w2 * x0; acc[2][1] += w2 * x1; acc[2][2] += w2 * x2; acc[2][3] += w2 * x3;
            acc[3][0] += w3 * x0; acc[3][1] += w3 * x1; acc[3][2] += w3 * x2; acc[3][3] += w3 * x3;
        }
        __syncthreads();
    }
    // reduce across kg
    #pragma unroll
    for (int i = 0; i < 4; i++)
        #pragma unroll
        for (int j = 0; j < 4; j++)
            red[kg * 1056 + (4 * rg + i) * 33 + (4 * bg + j)] = acc[i][j];
    __syncthreads();
    for (int p = tid; p < 1024; p += NTHR) {
        int rl = p >> 5, b = p & 31;
        float s = red[rl * 33 + b] + red[1056 + rl * 33 + b]
                + red[2112 + rl * 33 + b] + red[3168 + rl * 33 + b];
        gates_out[(size_t)(rowbase + rl) * 32 + b] = s;
    }
    __syncthreads();
}

// ---------------- attention for one b (block-local) ----------------
__device__ void attention_step(int b, int t, float* pool,
                               const float* __restrict__ ab,
                               const float* __restrict__ Wq,
                               const float* __restrict__ lk,
                               const float* __restrict__ Wloc,
                               const float* __restrict__ v_att,
                               const float* __restrict__ b_att,
                               const int* __restrict__ lens,
                               const float* __restrict__ enc,
                               float* __restrict__ align_out) {
    const int tid = threadIdx.x;
    const int warp = tid >> 5, lane = tid & 31;
    float* h_s  = pool;             // 1024
    float* q_s  = pool + 1024;      // 128
    float* wp_s = pool + 1152;      // 200
    float* wc_s = pool + 1352;      // 200
    float* e_s  = pool + 1552;      // 224
    float* feat = pool + 1776;      // 200*33 = 6600
    float* red8 = pool + 8376;      // 8

    // att pointwise -> h_att, c_att (in place, owned by this block)
    for (int d = tid; d < D_; d += NTHR) {
        float gi = g_gatt[(size_t)(0 * D_ + d) * 32 + b] + ab[d];
        float gf = g_gatt[(size_t)(1 * D_ + d) * 32 + b] + ab[D_ + d];
        float gc = g_gatt[(size_t)(2 * D_ + d) * 32 + b] + ab[2 * D_ + d];
        float go = g_gatt[(size_t)(3 * D_ + d) * 32 + b] + ab[3 * D_ + d];
        float c = sigf(gf) * g_catt[b * D_ + d] + sigf(gi) * tanhf(gc);
        float h = sigf(go) * tanhf(c);
        g_catt[b * D_ + d] = c;
        g_hatt[b * D_ + d] = h;
        h_s[d] = h;
    }
    if (tid < TENC) {
        wp_s[tid] = g_wprev[b * TENC + tid];
        wc_s[tid] = g_wcum[b * TENC + tid];
    }
    __syncthreads();

    // query[a] = Wq[a,:] . h  (+ b_att folded in)
    {
        int a = tid >> 1, half = tid & 1;
        const float* wq = Wq + (size_t)a * D_ + half * 512;
        const float* hh = h_s + half * 512;
        float q = 0.f;
        for (int k = 0; k < 512; k += 4) {
            float4 w4 = *(const float4*)(wq + k);
            q += w4.x * hh[k] + w4.y * hh[k + 1] + w4.z * hh[k + 2] + w4.w * hh[k + 3];
        }
        q += __shfl_xor_sync(0xffffffffu, q, 1);
        if (half == 0) q_s[a] = q + b_att[a];
    }
    __syncthreads();

    // location conv: feat[i][c]
    for (int idx = tid; idx < TENC * LF_; idx += NTHR) {
        int i = idx >> 5, c = idx & 31;
        const float* k0 = lk + c * (2 * KW_);
        float s = 0.f;
        #pragma unroll
        for (int k = 0; k < KW_; k++) {
            int j = i + k - PADW;
            if (j >= 0 && j < TENC) s += k0[k] * wp_s[j] + k0[KW_ + k] * wc_s[j];
        }
        feat[i * 33 + c] = s;
    }
    __syncthreads();

    // energy
    int len = lens[b];
    for (int i = warp; i < TENC; i += 8) {
        float part = 0.f;
        #pragma unroll
        for (int aa = 0; aa < 4; aa++) {
            int a = aa * 32 + lane;
            float s = q_s[a] + g_pm[((size_t)b * TENC + i) * A_ + a];
            const float* wl = Wloc + (size_t)a * LF_;
            #pragma unroll 8
            for (int c = 0; c < LF_; c++) s += wl[c] * feat[i * 33 + c];
            part += tanhf(s) * v_att[a];
        }
        part = warp_sum(part);
        if (lane == 0) e_s[i] = (i < len) ? part : -1e9f;
    }
    __syncthreads();

    // softmax over 200
    float e = (tid < TENC) ? e_s[tid] : -1e30f;
    float m = warp_max(e);
    if (lane == 0) red8[warp] = m;
    __syncthreads();
    if (tid == 0) {
        float mm = red8[0];
        #pragma unroll
        for (int i = 1; i < 8; i++) mm = fmaxf(mm, red8[i]);
        red8[0] = mm;
    }
    __syncthreads();
    float mx = red8[0];
    __syncthreads();
    float ex = (tid < TENC) ? __expf(e - mx) : 0.f;
    float ssum = warp_sum(ex);
    if (lane == 0) red8[warp] = ssum;
    __syncthreads();
    if (tid == 0) {
        float tot = 0.f;
        #pragma unroll
        for (int i = 0; i < 8; i++) tot += red8[i];
        red8[0] = tot;
    }
    __syncthreads();
    float inv = 1.f / red8[0];
    if (tid < TENC) {
        float w = ex * inv;
        e_s[tid] = w;
        g_wprev[b * TENC + tid] = w;
        g_wcum[b * TENC + tid] = wc_s[tid] + w;
        align_out[((size_t)b * TDEC + t) * TENC + tid] = w;
    }
    __syncthreads();

    // context[b] = sum_i w[i] enc[b,i,:]
    if (tid < 128) {
        const float4* encb = (const float4*)(enc + (size_t)b * TENC * E_) + tid;
        float4 acc = make_float4(0.f, 0.f, 0.f, 0.f);
        for (int i = 0; i < TENC; i++) {
            float w = e_s[i];
            float4 v = encb[(size_t)i * 128];
            acc.x += w * v.x; acc.y += w * v.y; acc.z += w * v.z; acc.w += w * v.w;
        }
        ((float4*)(g_ctx[t & 1] + b * E_))[tid] = acc;
    }
    __syncthreads();
}

// ---------------- gen pointwise + frame/stop for step tt (block-local b) ----------------
__device__ void genpw_frame(int b, int tt, float* pool,
                            const float* __restrict__ gb,
                            const float* __restrict__ fW, const float* __restrict__ fb,
                            const float* __restrict__ sW, const float* __restrict__ sb,
                            float* __restrict__ spec, float* __restrict__ stop) {
    const int tid = threadIdx.x;
    const int warp = tid >> 5, lane = tid & 31;
    float* proto = pool;  // [1536] = h_gen(1024) | ctx(512)

    for (int d = tid; d < D_; d += NTHR) {
        float gi = g_ggen[(size_t)(0 * D_ + d) * 32 + b] + gb[d];
        float gf = g_ggen[(size_t)(1 * D_ + d) * 32 + b] + gb[D_ + d];
        float gc = g_ggen[(size_t)(2 * D_ + d) * 32 + b] + gb[2 * D_ + d];
        float go = g_ggen[(size_t)(3 * D_ + d) * 32 + b] + gb[3 * D_ + d];
        float c = sigf(gf) * g_cgen[b * D_ + d] + sigf(gi) * tanhf(gc);
        float h = sigf(go) * tanhf(c);
        g_cgen[b * D_ + d] = c;
        g_hgen[b * D_ + d] = h;
        proto[d] = h;
    }
    const float* cx = g_ctx[tt & 1] + b * E_;
    for (int k = tid; k < E_; k += NTHR) proto[D_ + k] = cx[k];
    __syncthreads();

    for (int r = warp; r < M_ + 1; r += 8) {
        const float* w = (r < M_) ? (fW + (size_t)r * (D_ + E_)) : sW;
        float acc = 0.f;
        for (int k = lane * 4; k < D_ + E_; k += 128) {
            float4 w4 = *(const float4*)(w + k);
            float4 x4 = *(const float4*)(proto + k);
            acc += w4.x * x4.x + w4.y * x4.y + w4.z * x4.z + w4.w * x4.w;
        }
        acc = warp_sum(acc);
        if (lane == 0) {
            if (r < M_) spec[((size_t)b * TDEC + tt) * M_ + r] = acc + fb[r];
            else        stop[(size_t)b * TDEC + tt] = acc + sb[0];
        }
    }
    __syncthreads();
}

// ---------------- the persistent decoder ----------------
__global__ void __launch_bounds__(NTHR, 1)
decoder_kernel(const float* __restrict__ enc, const int* __restrict__ lens,
               const float* __restrict__ aWih, const float* __restrict__ aWhh, const float* __restrict__ ab,
               const float* __restrict__ gWih, const float* __restrict__ gWhh, const float* __restrict__ gb,
               const float* __restrict__ Wq, const float* __restrict__ lk,
               const float* __restrict__ Wloc, const float* __restrict__ v_att, const float* __restrict__ b_att,
               const float* __restrict__ fW, const float* __restrict__ fb,
               const float* __restrict__ sW, const float* __restrict__ sb,
               float* __restrict__ spec, float* __restrict__ stop, float* __restrict__ align_out) {
    __shared__ __align__(16) float pool[8704];
    const int blk = blockIdx.x;
    unsigned ls = g_sense;   // volatile read; stable until first barrier completes

    for (int t = 0; t < TDEC; t++) {
        // Phase A: att-LSTM gates. x = [pre_t(256) | ctx_{t-1}(512)], h = h_att
        lstm_gates(aWih, aWhh, P_ + E_,
                   g_pre + (size_t)t * P_, P_, TDEC * P_,
                   g_ctx[(t + 1) & 1], E_, E_,
                   g_hatt, D_,
                   g_gatt, pool, blk);
        grid_bar(ls);
        // Phase B
        if (blk < 32) {
            attention_step(blk, t, pool, ab, Wq, lk, Wloc, v_att, b_att, lens, enc, align_out);
        } else if (blk < 64 && t > 0) {
            genpw_frame(blk - 32, t - 1, pool, gb, fW, fb, sW, sb, spec, stop);
        }
        grid_bar(ls);
        // Phase C: gen-LSTM gates. x = [h_att(1024) | ctx_t(512)], h = h_gen
        lstm_gates(gWih, gWhh, D_ + E_,
                   g_hatt, D_, D_,
                   g_ctx[t & 1], E_, E_,
                   g_hgen, D_,
                   g_ggen, pool, blk);
    }
    grid_bar(ls);
    if (blk >= 32 && blk < 64) {
        genpw_frame(blk - 32, TDEC - 1, pool, gb, fW, fb, sW, sb, spec, stop);
    }
}

// ---------------- prologue kernels ----------------
__global__ void init_kernel() {
    int i = blockIdx.x * blockDim.x + threadIdx.x;   // 128*256 = 32768
    if (i < B_ * D_) { g_hatt[i] = 0.f; g_catt[i] = 0.f; g_hgen[i] = 0.f; g_cgen[i] = 0.f; }
    if (i < B_ * E_) { g_ctx[0][i] = 0.f; g_ctx[1][i] = 0.f; }
    if (i < B_ * TENC) { g_wprev[i] = 0.f; g_wcum[i] = 0.f; }
}

__global__ void prenet_kernel(const float* __restrict__ target,
                              const float* __restrict__ W1, const float* __restrict__ b1,
                              const float* __restrict__ W2, const float* __restrict__ b2) {
    int bt = blockIdx.x;
    int b = bt / TDEC, t = bt % TDEC;
    __shared__ float st[M_];
    __shared__ __align__(16) float sx1[P_];
    int tid = threadIdx.x;  // 256
    if (tid < M_) st[tid] = (t == 0) ? 0.f : target[((size_t)b * M_ + tid) * TDEC + (t - 1)];
    __syncthreads();
    float acc = b1[tid];
    const float* w = W1 + (size_t)tid * M_;
    #pragma unroll 8
    for (int m = 0; m < M_; m++) acc += w[m] * st[m];
    sx1[tid] = fmaxf(acc, 0.f);
    __syncthreads();
    float acc2 = b2[tid];
    const float* w2 = W2 + (size_t)tid * P_;
    for (int q = 0; q < P_; q += 4) {
        float4 ww = *(const float4*)(w2 + q);
        acc2 += ww.x * sx1[q] + ww.y * sx1[q + 1] + ww.z * sx1[q + 2] + ww.w * sx1[q + 3];
    }
    g_pre[((size_t)b * TDEC + t) * P_ + tid] = fmaxf(acc2, 0.f);
}

__global__ void procmem_kernel(const float* __restrict__ enc, const float* __restrict__ Wm) {
    int i = blockIdx.x, b = blockIdx.y;
    __shared__ __align__(16) float se[E_];
    for (int k = threadIdx.x; k < E_; k += 128) se[k] = enc[((size_t)b * TENC + i) * E_ + k];
    __syncthreads();
    int a = threadIdx.x;  // 128
    const float* w = Wm + (size_t)a * E_;
    float acc = 0.f;
    for (int k = 0; k < E_; k += 4) {
        float4 ww = *(const float4*)(w + k);
        acc += ww.x * se[k] + ww.y * se[k + 1] + ww.z * se[k + 2] + ww.w * se[k + 3];
    }
    g_pm[((size_t)b * TENC + i) * A_ + a] = acc;
}

// ---------------- launch ----------------
extern "C" void kernel_launch(void* const* d_in, const int* in_sizes, int n_in,
                              void* d_out, int out_size) {
    const float* enc    = (const float*)d_in[0];
    const int*   lens   = (const int*)d_in[1];
    const float* target = (const float*)d_in[2];
    // d_in[3] = teacher_forcing_ratio (==1; fully teacher-forced, unused)
    const float* pW1 = (const float*)d_in[4];
    const float* pb1 = (const float*)d_in[5];
    const float* pW2 = (const float*)d_in[6];
    const float* pb2 = (const float*)d_in[7];
    const float* aWih = (const float*)d_in[8];
    const float* aWhh = (const float*)d_in[9];
    const float* ab   = (const float*)d_in[10];
    const float* gWih = (const float*)d_in[11];
    const float* gWhh = (const float*)d_in[12];
    const float* gb   = (const float*)d_in[13];
    const float* Wq   = (const float*)d_in[14];
    const float* Wm   = (const float*)d_in[15];
    const float* lk   = (const float*)d_in[16];
    const float* Wloc = (const float*)d_in[17];
    const float* v_att = (const float*)d_in[18];
    const float* b_att = (const float*)d_in[19];
    const float* fW = (const float*)d_in[20];
    const float* fb = (const float*)d_in[21];
    const float* sW = (const float*)d_in[22];
    const float* sb = (const float*)d_in[23];

    float* out  = (float*)d_out;
    float* spec  = out;                                    // [B, Tdec, M]
    float* stop  = out + (size_t)B_ * TDEC * M_;           // [B, Tdec]
    float* align = stop + (size_t)B_ * TDEC;               // [B, Tdec, Tenc]

    init_kernel<<<128, 256>>>();
    prenet_kernel<<<B_ * TDEC, 256>>>(target, pW1, pb1, pW2, pb2);
    procmem_kernel<<<dim3(TENC, B_), 128>>>(enc, Wm);

    decoder_kernel<<<NBLK, NTHR>>>(enc, lens,
                                   aWih, aWhh, ab, gWih, gWhh, gb,
                                   Wq, lk, Wloc, v_att, b_att,
                                   fW, fb, sW, sb,
                                   spec, stop, align);
}

// round 3
// speedup vs baseline: 1.1189x; 1.1189x over previous
#include <cuda_runtime.h>
#include <math.h>

#define B_    32
#define TENC  200
#define E_    512
#define D_    1024
#define P_    256
#define M_    80
#define TDEC  600
#define A_    128
#define LF_   32
#define KW_   31
#define PADW  15
#define NBLK  128
#define NTHR  512
#define CHUNK 128
#define WPAD  132           // padded chunk stride (16B aligned, conflict-free)

// ---------------- device scratch (static, allocation-free) ----------------
__device__ float g_pre[(size_t)B_ * TDEC * P_];      // prenet out [b][t][256]
__device__ float g_pm[(size_t)B_ * TENC * A_];       // enc @ Wm^T [b][i][128]
__device__ float g_hatt[B_ * D_];
__device__ float g_catt[B_ * D_];
__device__ float g_hgen[B_ * D_];
__device__ float g_cgen[B_ * D_];
__device__ float g_ctx[2][B_ * E_];                  // ping-pong context
__device__ float g_wprev[B_ * TENC];
__device__ float g_wcum[B_ * TENC];
__device__ float g_gatt[(size_t)4 * D_ * B_];        // att gate preacts [row][b]
__device__ float g_ggen[(size_t)4 * D_ * B_];        // gen gate preacts [row][b]

// ---------------- grid barrier ----------------
__device__ unsigned g_count = 0;
__device__ volatile unsigned g_sense = 0;

__device__ __forceinline__ void grid_bar(unsigned& ls) {
    __syncthreads();
    ls ^= 1u;
    if (threadIdx.x == 0) {
        __threadfence();
        unsigned old = atomicAdd(&g_count, 1u);
        if (old == NBLK - 1) {
            atomicExch(&g_count, 0u);
            __threadfence();
            g_sense = ls;
        } else {
            while (g_sense != ls) { __nanosleep(64); }
            __threadfence();
        }
    }
    __syncthreads();
}

// ---------------- helpers ----------------
__device__ __forceinline__ float warp_sum(float v) {
    v += __shfl_xor_sync(0xffffffffu, v, 16);
    v += __shfl_xor_sync(0xffffffffu, v, 8);
    v += __shfl_xor_sync(0xffffffffu, v, 4);
    v += __shfl_xor_sync(0xffffffffu, v, 2);
    v += __shfl_xor_sync(0xffffffffu, v, 1);
    return v;
}
__device__ __forceinline__ float warp_max(float v) {
    v = fmaxf(v, __shfl_xor_sync(0xffffffffu, v, 16));
    v = fmaxf(v, __shfl_xor_sync(0xffffffffu, v, 8));
    v = fmaxf(v, __shfl_xor_sync(0xffffffffu, v, 4));
    v = fmaxf(v, __shfl_xor_sync(0xffffffffu, v, 2));
    v = fmaxf(v, __shfl_xor_sync(0xffffffffu, v, 1));
    return v;
}
__device__ __forceinline__ float sigf(float x) { return 1.f / (1.f + __expf(-x)); }

__device__ __forceinline__ void cp16(float* smem_dst, const float* gsrc) {
    unsigned s = (unsigned)__cvta_generic_to_shared(smem_dst);
    asm volatile("cp.async.cg.shared.global [%0], [%1], 16;" :: "r"(s), "l"(gsrc));
}
__device__ __forceinline__ void cp_commit() { asm volatile("cp.async.commit_group;"); }
__device__ __forceinline__ void cp_wait1() { asm volatile("cp.async.wait_group 1;"); }
__device__ __forceinline__ void cp_wait0() { asm volatile("cp.async.wait_group 0;"); }

// ---------------- LSTM gate GEMM: gates[4096 rows][32 b] ----------------
// Block handles 32 rows, 32 b, full K. 512 threads:
//   kg = tid>>6 (8 K-groups of 16 within a 128-chunk)
//   rg = (tid>>3)&7, bg = tid&7; thread tile rows {rg+8i}, b {bg+8j}, i,j in 0..3
// Double-buffered cp.async staging of [32][128] W and x tiles.
__device__ void lstm_gates(const float* __restrict__ Wih, const float* __restrict__ Whh,
                           int KX,
                           const float* s0, int l0, int st0,
                           const float* s1, int l1, int st1,
                           const float* s2, int st2,
                           float* __restrict__ gates_out, float* pool, int blk) {
    const int KTOT = KX + D_;
    const int NCH = KTOT / CHUNK;
    const int rowbase = blk * 32;
    const int tid = threadIdx.x;
    const int kg = tid >> 6;
    const int rg = (tid >> 3) & 7;
    const int bg = tid & 7;

    float* w_s = pool;                       // [2][32*132]
    float* x_s = pool + 2 * 32 * WPAD;       // [2][32*132]
    float* red = pool + 4 * 32 * WPAD;       // [8][32*33]

    // staging indices for this thread (4 cp.async per chunk: 2 W + 2 x)
    const int i0 = tid, i1 = tid + NTHR;     // in [0, 1024)
    const int wr0 = i0 >> 5, wc0 = (i0 & 31) * 4;
    const int wr1 = i1 >> 5, wc1 = (i1 & 31) * 4;

    #define STAGE(buf_, tb_)  do {                                              \
        int tb = (tb_);                                                          \
        float* wb = w_s + (buf_) * (32 * WPAD);                                   \
        float* xb = x_s + (buf_) * (32 * WPAD);                                   \
        {                                                                         \
            int k = tb + wc0;                                                     \
            const float* src = (k < KX) ? Wih + (size_t)(rowbase + wr0) * KX + k  \
                                        : Whh + (size_t)(rowbase + wr0) * D_ + (k - KX); \
            cp16(wb + wr0 * WPAD + wc0, src);                                     \
        }                                                                         \
        {                                                                         \
            int k = tb + wc1;                                                     \
            const float* src = (k < KX) ? Wih + (size_t)(rowbase + wr1) * KX + k  \
                                        : Whh + (size_t)(rowbase + wr1) * D_ + (k - KX); \
            cp16(wb + wr1 * WPAD + wc1, src);                                     \
        }                                                                         \
        {                                                                         \
            int k = tb + wc0;                                                     \
            const float* src;                                                     \
            if (k < l0)           src = s0 + (size_t)wr0 * st0 + k;               \
            else if (k < l0 + l1) src = s1 + (size_t)wr0 * st1 + (k - l0);        \
            else                  src = s2 + (size_t)wr0 * st2 + (k - l0 - l1);   \
            cp16(xb + wr0 * WPAD + wc0, src);                                     \
        }                                                                         \
        {                                                                         \
            int k = tb + wc1;                                                     \
            const float* src;                                                     \
            if (k < l0)           src = s1 ? ((k < l0) ? s0 + (size_t)wr1 * st0 + k : s0) : s0; \
            else                  src = s0;                                       \
            if (k < l0)           src = s0 + (size_t)wr1 * st0 + k;               \
            else if (k < l0 + l1) src = s1 + (size_t)wr1 * st1 + (k - l0);        \
            else                  src = s2 + (size_t)wr1 * st2 + (k - l0 - l1);   \
            cp16(xb + wr1 * WPAD + wc1, src);                                     \
        }                                                                         \
    } while (0)

    float acc[4][4];
    #pragma unroll
    for (int i = 0; i < 4; i++)
        #pragma unroll
        for (int j = 0; j < 4; j++) acc[i][j] = 0.f;

    STAGE(0, 0);
    cp_commit();

    for (int c = 0; c < NCH; c++) {
        if (c + 1 < NCH) { STAGE((c + 1) & 1, (c + 1) * CHUNK); cp_commit(); cp_wait1(); }
        else             { cp_wait0(); }
        __syncthreads();

        const float* wp = w_s + (c & 1) * (32 * WPAD) + rg * WPAD + kg * 16;
        const float* xp = x_s + (c & 1) * (32 * WPAD) + bg * WPAD + kg * 16;
        #pragma unroll
        for (int kk = 0; kk < 16; kk++) {
            float w0 = wp[kk], w1 = wp[kk + 8 * WPAD], w2 = wp[kk + 16 * WPAD], w3 = wp[kk + 24 * WPAD];
            float x0 = xp[kk], x1 = xp[kk + 8 * WPAD], x2 = xp[kk + 16 * WPAD], x3 = xp[kk + 24 * WPAD];
            acc[0][0] += w0 * x0; acc[0][1] += w0 * x1; acc[0][2] += w0 * x2; acc[0][3] += w0 * x3;
            acc[1][0] += w1 * x0; acc[1][1] += w1 * x1; acc[1][2] += w1 * x2; acc[1][3] += w1 * x3;
            acc[2][0] += w2 * x0; acc[2][1] += w2 * x1; acc[2][2] += w2 * x2; acc[2][3] += w2 * x3;
            acc[3][0] += w3 * x0; acc[3][1] += w3 * x1; acc[3][2] += w3 * x2; acc[3][3] += w3 * x3;
        }
        __syncthreads();
    }
    #undef STAGE

    // reduce across kg groups
    #pragma unroll
    for (int i = 0; i < 4; i++)
        #pragma unroll
        for (int j = 0; j < 4; j++)
            red[kg * (32 * 33) + (rg + 8 * i) * 33 + (bg + 8 * j)] = acc[i][j];
    __syncthreads();
    for (int p = tid; p < 1024; p += NTHR) {
        int r = p >> 5, b = p & 31;
        float s = 0.f;
        #pragma unroll
        for (int q = 0; q < 8; q++) s += red[q * (32 * 33) + r * 33 + b];
        gates_out[(size_t)(rowbase + r) * 32 + b] = s;
    }
    __syncthreads();
}

// ---------------- attention for one b (block-local, 512 threads) ----------------
__device__ void attention_step(int b, int t, float* pool,
                               const float* __restrict__ ab,
                               const float* __restrict__ Wq,
                               const float* __restrict__ lk,
                               const float* __restrict__ Wloc,
                               const float* __restrict__ v_att,
                               const float* __restrict__ b_att,
                               const int* __restrict__ lens,
                               const float* __restrict__ enc,
                               float* __restrict__ align_out) {
    const int tid = threadIdx.x;
    const int warp = tid >> 5, lane = tid & 31;
    float* h_s   = pool;             // 1024
    float* q_s   = pool + 1024;      // 128
    float* wp_s  = pool + 1152;      // 200
    float* wc_s  = pool + 1352;      // 200
    float* e_s   = pool + 1552;      // 224
    float* feat  = pool + 1776;      // 200*33 = 6600
    float* red16 = pool + 8376;      // 16

    // att pointwise -> h_att, c_att
    for (int d = tid; d < D_; d += NTHR) {
        float gi = g_gatt[(size_t)(0 * D_ + d) * 32 + b] + ab[d];
        float gf = g_gatt[(size_t)(1 * D_ + d) * 32 + b] + ab[D_ + d];
        float gc = g_gatt[(size_t)(2 * D_ + d) * 32 + b] + ab[2 * D_ + d];
        float go = g_gatt[(size_t)(3 * D_ + d) * 32 + b] + ab[3 * D_ + d];
        float c = sigf(gf) * g_catt[b * D_ + d] + sigf(gi) * tanhf(gc);
        float h = sigf(go) * tanhf(c);
        g_catt[b * D_ + d] = c;
        g_hatt[b * D_ + d] = h;
        h_s[d] = h;
    }
    if (tid < TENC) {
        wp_s[tid] = g_wprev[b * TENC + tid];
        wc_s[tid] = g_wcum[b * TENC + tid];
    }
    __syncthreads();

    // query[a] = Wq[a,:] . h + b_att[a]   (4 threads per a, 256 k each)
    {
        int a = tid >> 2, q4 = tid & 3;
        const float* wq = Wq + (size_t)a * D_ + q4 * 256;
        const float* hh = h_s + q4 * 256;
        float q = 0.f;
        for (int k = 0; k < 256; k += 4) {
            float4 w4 = *(const float4*)(wq + k);
            q += w4.x * hh[k] + w4.y * hh[k + 1] + w4.z * hh[k + 2] + w4.w * hh[k + 3];
        }
        q += __shfl_xor_sync(0xffffffffu, q, 1);
        q += __shfl_xor_sync(0xffffffffu, q, 2);
        if (q4 == 0) q_s[a] = q + b_att[a];
    }
    __syncthreads();

    // location conv: feat[i][c]
    for (int idx = tid; idx < TENC * LF_; idx += NTHR) {
        int i = idx >> 5, c = idx & 31;
        const float* k0 = lk + c * (2 * KW_);
        float s = 0.f;
        #pragma unroll
        for (int k = 0; k < KW_; k++) {
            int j = i + k - PADW;
            if (j >= 0 && j < TENC) s += k0[k] * wp_s[j] + k0[KW_ + k] * wc_s[j];
        }
        feat[i * 33 + c] = s;
    }
    __syncthreads();

    // energy
    int len = lens[b];
    for (int i = warp; i < TENC; i += 16) {
        float part = 0.f;
        #pragma unroll
        for (int aa = 0; aa < 4; aa++) {
            int a = aa * 32 + lane;
            float s = q_s[a] + g_pm[((size_t)b * TENC + i) * A_ + a];
            const float* wl = Wloc + (size_t)a * LF_;
            #pragma unroll 8
            for (int c = 0; c < LF_; c++) s += wl[c] * feat[i * 33 + c];
            part += tanhf(s) * v_att[a];
        }
        part = warp_sum(part);
        if (lane == 0) e_s[i] = (i < len) ? part : -1e9f;
    }
    __syncthreads();

    // softmax over 200
    float e = (tid < TENC) ? e_s[tid] : -1e30f;
    float m = warp_max(e);
    if (lane == 0) red16[warp] = m;
    __syncthreads();
    if (tid == 0) {
        float mm = red16[0];
        #pragma unroll
        for (int i = 1; i < 16; i++) mm = fmaxf(mm, red16[i]);
        red16[0] = mm;
    }
    __syncthreads();
    float mx = red16[0];
    __syncthreads();
    float ex = (tid < TENC) ? __expf(e - mx) : 0.f;
    float ssum = warp_sum(ex);
    if (lane == 0) red16[warp] = ssum;
    __syncthreads();
    if (tid == 0) {
        float tot = 0.f;
        #pragma unroll
        for (int i = 0; i < 16; i++) tot += red16[i];
        red16[0] = tot;
    }
    __syncthreads();
    float inv = 1.f / red16[0];
    if (tid < TENC) {
        float w = ex * inv;
        e_s[tid] = w;
        g_wprev[b * TENC + tid] = w;
        g_wcum[b * TENC + tid] = wc_s[tid] + w;
        align_out[((size_t)b * TDEC + t) * TENC + tid] = w;
    }
    __syncthreads();

    // context[b] = sum_i w[i] enc[b,i,:]  (256 threads: 2 halves of i-range)
    if (tid < 256) {
        int col = tid & 127, half = tid >> 7;
        const float4* encb = (const float4*)(enc + (size_t)b * TENC * E_) + col;
        float4 acc = make_float4(0.f, 0.f, 0.f, 0.f);
        for (int i = half * 100; i < half * 100 + 100; i++) {
            float w = e_s[i];
            float4 v = encb[(size_t)i * 128];
            acc.x += w * v.x; acc.y += w * v.y; acc.z += w * v.z; acc.w += w * v.w;
        }
        // combine halves via smem (reuse feat region)
        float* part = feat;   // 256*4 floats
        ((float4*)part)[tid] = acc;
    }
    __syncthreads();
    if (tid < 128) {
        float4 a0 = ((float4*)feat)[tid];
        float4 a1 = ((float4*)feat)[tid + 128];
        float4 r = make_float4(a0.x + a1.x, a0.y + a1.y, a0.z + a1.z, a0.w + a1.w);
        ((float4*)(g_ctx[t & 1] + b * E_))[tid] = r;
    }
    __syncthreads();
}

// ---------------- gen pointwise + frame/stop for step tt ----------------
__device__ void genpw_frame(int b, int tt, float* pool,
                            const float* __restrict__ gb,
                            const float* __restrict__ fW, const float* __restrict__ fb,
                            const float* __restrict__ sW, const float* __restrict__ sb,
                            float* __restrict__ spec, float* __restrict__ stop) {
    const int tid = threadIdx.x;
    const int warp = tid >> 5, lane = tid & 31;
    float* proto = pool;  // [1536] = h_gen(1024) | ctx(512)

    for (int d = tid; d < D_; d += NTHR) {
        float gi = g_ggen[(size_t)(0 * D_ + d) * 32 + b] + gb[d];
        float gf = g_ggen[(size_t)(1 * D_ + d) * 32 + b] + gb[D_ + d];
        float gc = g_ggen[(size_t)(2 * D_ + d) * 32 + b] + gb[2 * D_ + d];
        float go = g_ggen[(size_t)(3 * D_ + d) * 32 + b] + gb[3 * D_ + d];
        float c = sigf(gf) * g_cgen[b * D_ + d] + sigf(gi) * tanhf(gc);
        float h = sigf(go) * tanhf(c);
        g_cgen[b * D_ + d] = c;
        g_hgen[b * D_ + d] = h;
        proto[d] = h;
    }
    const float* cx = g_ctx[tt & 1] + b * E_;
    for (int k = tid; k < E_; k += NTHR) proto[D_ + k] = cx[k];
    __syncthreads();

    for (int r = warp; r < M_ + 1; r += 16) {
        const float* w = (r < M_) ? (fW + (size_t)r * (D_ + E_)) : sW;
        float acc = 0.f;
        for (int k = lane * 4; k < D_ + E_; k += 128) {
            float4 w4 = *(const float4*)(w + k);
            float4 x4 = *(const float4*)(proto + k);
            acc += w4.x * x4.x + w4.y * x4.y + w4.z * x4.z + w4.w * x4.w;
        }
        acc = warp_sum(acc);
        if (lane == 0) {
            if (r < M_) spec[((size_t)b * TDEC + tt) * M_ + r] = acc + fb[r];
            else        stop[(size_t)b * TDEC + tt] = acc + sb[0];
        }
    }
    __syncthreads();
}

// ---------------- the persistent decoder ----------------
__global__ void __launch_bounds__(NTHR, 1)
decoder_kernel(const float* __restrict__ enc, const int* __restrict__ lens,
               const float* __restrict__ aWih, const float* __restrict__ aWhh, const float* __restrict__ ab,
               const float* __restrict__ gWih, const float* __restrict__ gWhh, const float* __restrict__ gb,
               const float* __restrict__ Wq, const float* __restrict__ lk,
               const float* __restrict__ Wloc, const float* __restrict__ v_att, const float* __restrict__ b_att,
               const float* __restrict__ fW, const float* __restrict__ fb,
               const float* __restrict__ sW, const float* __restrict__ sb,
               float* __restrict__ spec, float* __restrict__ stop, float* __restrict__ align_out) {
    extern __shared__ __align__(16) float pool[];
    const int blk = blockIdx.x;
    unsigned ls = g_sense;

    for (int t = 0; t < TDEC; t++) {
        // Phase A: att-LSTM gates. x = [pre_t(256) | ctx_{t-1}(512)], h = h_att
        lstm_gates(aWih, aWhh, P_ + E_,
                   g_pre + (size_t)t * P_, P_, TDEC * P_,
                   g_ctx[(t + 1) & 1], E_, E_,
                   g_hatt, D_,
                   g_gatt, pool, blk);
        grid_bar(ls);
        // Phase B
        if (blk < 32) {
            attention_step(blk, t, pool, ab, Wq, lk, Wloc, v_att, b_att, lens, enc, align_out);
        } else if (blk < 64 && t > 0) {
            genpw_frame(blk - 32, t - 1, pool, gb, fW, fb, sW, sb, spec, stop);
        }
        grid_bar(ls);
        // Phase C: gen-LSTM gates. x = [h_att(1024) | ctx_t(512)], h = h_gen
        lstm_gates(gWih, gWhh, D_ + E_,
                   g_hatt, D_, D_,
                   g_ctx[t & 1], E_, E_,
                   g_hgen, D_,
                   g_ggen, pool, blk);
    }
    grid_bar(ls);
    if (blk >= 32 && blk < 64) {
        genpw_frame(blk - 32, TDEC - 1, pool, gb, fW, fb, sW, sb, spec, stop);
    }
}

// ---------------- prologue kernels ----------------
__global__ void init_kernel() {
    int i = blockIdx.x * blockDim.x + threadIdx.x;   // 128*256 = 32768
    if (i < B_ * D_) { g_hatt[i] = 0.f; g_catt[i] = 0.f; g_hgen[i] = 0.f; g_cgen[i] = 0.f; }
    if (i < B_ * E_) { g_ctx[0][i] = 0.f; g_ctx[1][i] = 0.f; }
    if (i < B_ * TENC) { g_wprev[i] = 0.f; g_wcum[i] = 0.f; }
}

__global__ void prenet_kernel(const float* __restrict__ target,
                              const float* __restrict__ W1, const float* __restrict__ b1,
                              const float* __restrict__ W2, const float* __restrict__ b2) {
    int bt = blockIdx.x;
    int b = bt / TDEC, t = bt % TDEC;
    __shared__ float st[M_];
    __shared__ __align__(16) float sx1[P_];
    int tid = threadIdx.x;  // 256
    if (tid < M_) st[tid] = (t == 0) ? 0.f : target[((size_t)b * M_ + tid) * TDEC + (t - 1)];
    __syncthreads();
    float acc = b1[tid];
    const float* w = W1 + (size_t)tid * M_;
    #pragma unroll 8
    for (int m = 0; m < M_; m++) acc += w[m] * st[m];
    sx1[tid] = fmaxf(acc, 0.f);
    __syncthreads();
    float acc2 = b2[tid];
    const float* w2 = W2 + (size_t)tid * P_;
    for (int q = 0; q < P_; q += 4) {
        float4 ww = *(const float4*)(w2 + q);
        acc2 += ww.x * sx1[q] + ww.y * sx1[q + 1] + ww.z * sx1[q + 2] + ww.w * sx1[q + 3];
    }
    g_pre[((size_t)b * TDEC + t) * P_ + tid] = fmaxf(acc2, 0.f);
}

__global__ void procmem_kernel(const float* __restrict__ enc, const float* __restrict__ Wm) {
    int i = blockIdx.x, b = blockIdx.y;
    __shared__ __align__(16) float se[E_];
    for (int k = threadIdx.x; k < E_; k += 128) se[k] = enc[((size_t)b * TENC + i) * E_ + k];
    __syncthreads();
    int a = threadIdx.x;  // 128
    const float* w = Wm + (size_t)a * E_;
    float acc = 0.f;
    for (int k = 0; k < E_; k += 4) {
        float4 ww = *(const float4*)(w + k);
        acc += ww.x * se[k] + ww.y * se[k + 1] + ww.z * se[k + 2] + ww.w * se[k + 3];
    }
    g_pm[((size_t)b * TENC + i) * A_ + a] = acc;
}

// ---------------- launch ----------------
extern "C" void kernel_launch(void* const* d_in, const int* in_sizes, int n_in,
                              void* d_out, int out_size) {
    const float* enc    = (const float*)d_in[0];
    const int*   lens   = (const int*)d_in[1];
    const float* target = (const float*)d_in[2];
    // d_in[3] = teacher_forcing_ratio (==1; fully teacher-forced, unused)
    const float* pW1 = (const float*)d_in[4];
    const float* pb1 = (const float*)d_in[5];
    const float* pW2 = (const float*)d_in[6];
    const float* pb2 = (const float*)d_in[7];
    const float* aWih = (const float*)d_in[8];
    const float* aWhh = (const float*)d_in[9];
    const float* ab   = (const float*)d_in[10];
    const float* gWih = (const float*)d_in[11];
    const float* gWhh = (const float*)d_in[12];
    const float* gb   = (const float*)d_in[13];
    const float* Wq   = (const float*)d_in[14];
    const float* Wm   = (const float*)d_in[15];
    const float* lk   = (const float*)d_in[16];
    const float* Wloc = (const float*)d_in[17];
    const float* v_att = (const float*)d_in[18];
    const float* b_att = (const float*)d_in[19];
    const float* fW = (const float*)d_in[20];
    const float* fb = (const float*)d_in[21];
    const float* sW = (const float*)d_in[22];
    const float* sb = (const float*)d_in[23];

    float* out  = (float*)d_out;
    float* spec  = out;                                    // [B, Tdec, M]
    float* stop  = out + (size_t)B_ * TDEC * M_;           // [B, Tdec]
    float* align = stop + (size_t)B_ * TDEC;               // [B, Tdec, Tenc]

    // dynamic smem: 2x(32*132) W + 2x(32*132) x + 8x(32*33) reduce = 25344 floats
    const int smem_bytes = 25344 * 4;
    static int configured = 0;
    if (!configured) {
        cudaFuncSetAttribute(decoder_kernel, cudaFuncAttributeMaxDynamicSharedMemorySize, smem_bytes);
        configured = 1;
    }

    init_kernel<<<128, 256>>>();
    prenet_kernel<<<B_ * TDEC, 256>>>(target, pW1, pb1, pW2, pb2);
    procmem_kernel<<<dim3(TENC, B_), 128>>>(enc, Wm);

    decoder_kernel<<<NBLK, NTHR, smem_bytes>>>(enc, lens,
                                               aWih, aWhh, ab, gWih, gWhh, gb,
                                               Wq, lk, Wloc, v_att, b_att,
                                               fW, fb, sW, sb,
                                               spec, stop, align);
}

// round 4
// speedup vs baseline: 4.0036x; 3.5783x over previous
#include <cuda_runtime.h>
#include <math.h>

#define B_    32
#define TENC  200
#define E_    512
#define D_    1024
#define P_    256
#define M_    80
#define TDEC  600
#define A_    128
#define LF_   32
#define KW_   31
#define PADW  15
#define NBLK  128
#define NTHR  512
#define CHUNK 128
#define WPAD  132           // padded chunk stride in floats (33 float4, conflict-free)

// ---------------- device scratch (static, allocation-free) ----------------
__device__ __align__(16) float g_pre[(size_t)B_ * TDEC * P_];   // prenet out [b][t][256]
__device__ __align__(16) float g_pm[(size_t)B_ * TENC * A_];    // enc @ Wm^T [b][i][128]
__device__ __align__(16) float g_hatt[B_ * D_];
__device__ __align__(16) float g_catt[B_ * D_];
__device__ __align__(16) float g_hgen[B_ * D_];
__device__ __align__(16) float g_cgen[B_ * D_];
__device__ __align__(16) float g_ctx[2][B_ * E_];               // ping-pong context
__device__ __align__(16) float g_wprev[B_ * TENC];
__device__ __align__(16) float g_wcum[B_ * TENC];
__device__ __align__(16) float g_gatt[(size_t)B_ * 4 * D_];     // att gate preacts [b][row]
__device__ __align__(16) float g_ggen[(size_t)B_ * 4 * D_];     // gen gate preacts [b][row]

// ---------------- grid barrier ----------------
__device__ unsigned g_count = 0;
__device__ volatile unsigned g_sense = 0;

__device__ __forceinline__ void grid_bar(unsigned& ls) {
    __syncthreads();
    ls ^= 1u;
    if (threadIdx.x == 0) {
        __threadfence();
        unsigned old = atomicAdd(&g_count, 1u);
        if (old == NBLK - 1) {
            atomicExch(&g_count, 0u);
            __threadfence();
            g_sense = ls;
        } else {
            while (g_sense != ls) { __nanosleep(64); }
            __threadfence();
        }
    }
    __syncthreads();
}

// ---------------- helpers ----------------
__device__ __forceinline__ float warp_sum(float v) {
    v += __shfl_xor_sync(0xffffffffu, v, 16);
    v += __shfl_xor_sync(0xffffffffu, v, 8);
    v += __shfl_xor_sync(0xffffffffu, v, 4);
    v += __shfl_xor_sync(0xffffffffu, v, 2);
    v += __shfl_xor_sync(0xffffffffu, v, 1);
    return v;
}
__device__ __forceinline__ float warp_max(float v) {
    v = fmaxf(v, __shfl_xor_sync(0xffffffffu, v, 16));
    v = fmaxf(v, __shfl_xor_sync(0xffffffffu, v, 8));
    v = fmaxf(v, __shfl_xor_sync(0xffffffffu, v, 4));
    v = fmaxf(v, __shfl_xor_sync(0xffffffffu, v, 2));
    v = fmaxf(v, __shfl_xor_sync(0xffffffffu, v, 1));
    return v;
}
__device__ __forceinline__ float sigf(float x) { return 1.f / (1.f + __expf(-x)); }

__device__ __forceinline__ void cp16(float* smem_dst, const float* gsrc) {
    unsigned s = (unsigned)__cvta_generic_to_shared(smem_dst);
    asm volatile("cp.async.cg.shared.global [%0], [%1], 16;" :: "r"(s), "l"(gsrc));
}
__device__ __forceinline__ void cp_commit() { asm volatile("cp.async.commit_group;"); }
__device__ __forceinline__ void cp_wait1() { asm volatile("cp.async.wait_group 1;"); }
__device__ __forceinline__ void cp_wait0() { asm volatile("cp.async.wait_group 0;"); }

// ---------------- LSTM gate GEMM: gates[b][4096 rows] ----------------
// Block = 32 rows x 32 b, full K. Double-buffered cp.async, float4 LDS inner.
__device__ void lstm_gates(const float* __restrict__ Wih, const float* __restrict__ Whh,
                           int KX,
                           const float* s0, int l0, int st0,
                           const float* s1, int l1, int st1,
                           const float* s2, int st2,
                           float* __restrict__ gates_out, float* pool, int blk) {
    const int KTOT = KX + D_;
    const int NCH = KTOT / CHUNK;
    const int rowbase = blk * 32;
    const int tid = threadIdx.x;
    const int kg = tid >> 6;            // 0..7 K-group
    const int rg = (tid >> 3) & 7;      // row group
    const int bg = tid & 7;             // batch group

    float* w_s = pool;                       // [2][32*132]
    float* x_s = pool + 2 * 32 * WPAD;       // [2][32*132]
    float* red = pool + 4 * 32 * WPAD;       // [8][32*33]

    const int i0 = tid, i1 = tid + NTHR;
    const int wr0 = i0 >> 5, wc0 = (i0 & 31) * 4;
    const int wr1 = i1 >> 5, wc1 = (i1 & 31) * 4;

    #define STAGE(buf_, tb_)  do {                                               \
        int tb = (tb_);                                                           \
        float* wb = w_s + (buf_) * (32 * WPAD);                                    \
        float* xb = x_s + (buf_) * (32 * WPAD);                                    \
        {                                                                          \
            int k = tb + wc0;                                                      \
            const float* src = (k < KX) ? Wih + (size_t)(rowbase + wr0) * KX + k   \
                                        : Whh + (size_t)(rowbase + wr0) * D_ + (k - KX); \
            cp16(wb + wr0 * WPAD + wc0, src);                                      \
        }                                                                          \
        {                                                                          \
            int k = tb + wc1;                                                      \
            const float* src = (k < KX) ? Wih + (size_t)(rowbase + wr1) * KX + k   \
                                        : Whh + (size_t)(rowbase + wr1) * D_ + (k - KX); \
            cp16(wb + wr1 * WPAD + wc1, src);                                      \
        }                                                                          \
        {                                                                          \
            int k = tb + wc0;                                                      \
            const float* src;                                                      \
            if (k < l0)           src = s0 + (size_t)wr0 * st0 + k;                \
            else if (k < l0 + l1) src = s1 + (size_t)wr0 * st1 + (k - l0);         \
            else                  src = s2 + (size_t)wr0 * st2 + (k - l0 - l1);    \
            cp16(xb + wr0 * WPAD + wc0, src);                                      \
        }                                                                          \
        {                                                                          \
            int k = tb + wc1;                                                      \
            const float* src;                                                      \
            if (k < l0)           src = s0 + (size_t)wr1 * st0 + k;                \
            else if (k < l0 + l1) src = s1 + (size_t)wr1 * st1 + (k - l0);         \
            else                  src = s2 + (size_t)wr1 * st2 + (k - l0 - l1);    \
            cp16(xb + wr1 * WPAD + wc1, src);                                      \
        }                                                                          \
    } while (0)

    float acc[4][4];
    #pragma unroll
    for (int i = 0; i < 4; i++)
        #pragma unroll
        for (int j = 0; j < 4; j++) acc[i][j] = 0.f;

    STAGE(0, 0);
    cp_commit();

    for (int c = 0; c < NCH; c++) {
        if (c + 1 < NCH) { STAGE((c + 1) & 1, (c + 1) * CHUNK); cp_commit(); cp_wait1(); }
        else             { cp_wait0(); }
        __syncthreads();

        const float4* wp4 = (const float4*)(w_s + (c & 1) * (32 * WPAD)) + rg * 33 + kg * 4;
        const float4* xp4 = (const float4*)(x_s + (c & 1) * (32 * WPAD)) + bg * 33 + kg * 4;
        #pragma unroll
        for (int kk = 0; kk < 4; kk++) {
            float4 w0 = wp4[kk], w1 = wp4[kk + 8 * 33], w2 = wp4[kk + 16 * 33], w3 = wp4[kk + 24 * 33];
            float4 x0 = xp4[kk], x1 = xp4[kk + 8 * 33], x2 = xp4[kk + 16 * 33], x3 = xp4[kk + 24 * 33];
            acc[0][0] += w0.x*x0.x + w0.y*x0.y + w0.z*x0.z + w0.w*x0.w;
            acc[0][1] += w0.x*x1.x + w0.y*x1.y + w0.z*x1.z + w0.w*x1.w;
            acc[0][2] += w0.x*x2.x + w0.y*x2.y + w0.z*x2.z + w0.w*x2.w;
            acc[0][3] += w0.x*x3.x + w0.y*x3.y + w0.z*x3.z + w0.w*x3.w;
            acc[1][0] += w1.x*x0.x + w1.y*x0.y + w1.z*x0.z + w1.w*x0.w;
            acc[1][1] += w1.x*x1.x + w1.y*x1.y + w1.z*x1.z + w1.w*x1.w;
            acc[1][2] += w1.x*x2.x + w1.y*x2.y + w1.z*x2.z + w1.w*x2.w;
            acc[1][3] += w1.x*x3.x + w1.y*x3.y + w1.z*x3.z + w1.w*x3.w;
            acc[2][0] += w2.x*x0.x + w2.y*x0.y + w2.z*x0.z + w2.w*x0.w;
            acc[2][1] += w2.x*x1.x + w2.y*x1.y + w2.z*x1.z + w2.w*x1.w;
            acc[2][2] += w2.x*x2.x + w2.y*x2.y + w2.z*x2.z + w2.w*x2.w;
            acc[2][3] += w2.x*x3.x + w2.y*x3.y + w2.z*x3.z + w2.w*x3.w;
            acc[3][0] += w3.x*x0.x + w3.y*x0.y + w3.z*x0.z + w3.w*x0.w;
            acc[3][1] += w3.x*x1.x + w3.y*x1.y + w3.z*x1.z + w3.w*x1.w;
            acc[3][2] += w3.x*x2.x + w3.y*x2.y + w3.z*x2.z + w3.w*x2.w;
            acc[3][3] += w3.x*x3.x + w3.y*x3.y + w3.z*x3.z + w3.w*x3.w;
        }
        __syncthreads();
    }
    #undef STAGE

    // reduce across 8 K-groups
    #pragma unroll
    for (int i = 0; i < 4; i++)
        #pragma unroll
        for (int j = 0; j < 4; j++)
            red[kg * (32 * 33) + (rg + 8 * i) * 33 + (bg + 8 * j)] = acc[i][j];
    __syncthreads();
    for (int p = tid; p < 1024; p += NTHR) {
        int b = p >> 5, r = p & 31;     // lanes -> consecutive rows: coalesced store
        float s = 0.f;
        #pragma unroll
        for (int q = 0; q < 8; q++) s += red[q * (32 * 33) + r * 33 + b];
        gates_out[(size_t)b * (4 * D_) + rowbase + r] = s;
    }
    __syncthreads();
}

// ---------------- attention for one b (block-local, 512 threads) ----------------
__device__ void attention_step(int b, int t, float* pool,
                               const float* __restrict__ ab,
                               const float* __restrict__ Wq,
                               const float* __restrict__ lk,
                               const float* __restrict__ Wloc,
                               const float* __restrict__ v_att,
                               const float* __restrict__ b_att,
                               const int* __restrict__ lens,
                               const float* __restrict__ enc,
                               float* __restrict__ align_out) {
    const int tid = threadIdx.x;
    const int warp = tid >> 5, lane = tid & 31;
    float* h_s   = pool;             // 1024
    float* q_s   = pool + 1024;      // 128
    float* wp_s  = pool + 1152;      // 200
    float* wc_s  = pool + 1352;      // 200
    float* e_s   = pool + 1552;      // 224
    float* feat  = pool + 1776;      // 200*33 = 6600
    float* red16 = pool + 8376;      // 16
    float* wlocT = pool + 8400;      // 32*129 = 4128  (WlocT[c][a], padded)

    // att pointwise -> h_att, c_att (coalesced: gates laid out [b][row])
    const float* gat = g_gatt + (size_t)b * (4 * D_);
    for (int d = tid; d < D_; d += NTHR) {
        float gi = gat[d]           + ab[d];
        float gf = gat[D_ + d]      + ab[D_ + d];
        float gc = gat[2 * D_ + d]  + ab[2 * D_ + d];
        float go = gat[3 * D_ + d]  + ab[3 * D_ + d];
        float c = sigf(gf) * g_catt[b * D_ + d] + sigf(gi) * tanhf(gc);
        float h = sigf(go) * tanhf(c);
        g_catt[b * D_ + d] = c;
        g_hatt[b * D_ + d] = h;
        h_s[d] = h;
    }
    if (tid < TENC) {
        wp_s[tid] = g_wprev[b * TENC + tid];
        wc_s[tid] = g_wcum[b * TENC + tid];
    }
    // stage Wloc transposed: wlocT[c*129 + a] = Wloc[a*32 + c]  (coalesced read)
    for (int idx = tid; idx < A_ * LF_; idx += NTHR) {
        int a = idx >> 5, c = idx & 31;
        wlocT[c * 129 + a] = Wloc[idx];
    }
    __syncthreads();

    // query: warp per 8 outputs, lane over k (coalesced float4)
    {
        const float4* h4 = (const float4*)h_s;
        for (int a = warp * 8; a < warp * 8 + 8; a++) {
            const float4* wq = (const float4*)(Wq + (size_t)a * D_);
            float acc = 0.f;
            #pragma unroll
            for (int kk = 0; kk < 8; kk++) {
                float4 w4 = wq[lane + 32 * kk];
                float4 x4 = h4[lane + 32 * kk];
                acc += w4.x * x4.x + w4.y * x4.y + w4.z * x4.z + w4.w * x4.w;
            }
            acc = warp_sum(acc);
            if (lane == 0) q_s[a] = acc + b_att[a];
        }
    }
    __syncthreads();

    // location conv: feat[i][c]
    for (int idx = tid; idx < TENC * LF_; idx += NTHR) {
        int i = idx >> 5, c = idx & 31;
        const float* k0 = lk + c * (2 * KW_);
        float s = 0.f;
        #pragma unroll
        for (int k = 0; k < KW_; k++) {
            int j = i + k - PADW;
            if (j >= 0 && j < TENC) s += k0[k] * wp_s[j] + k0[KW_ + k] * wc_s[j];
        }
        feat[i * 33 + c] = s;
    }
    __syncthreads();

    // energy (Wloc from transposed smem: conflict-free)
    int len = lens[b];
    for (int i = warp; i < TENC; i += 16) {
        const float* fi = feat + i * 33;
        const float* pm = g_pm + ((size_t)b * TENC + i) * A_;
        float part = 0.f;
        #pragma unroll
        for (int aa = 0; aa < 4; aa++) {
            int a = aa * 32 + lane;
            float s = q_s[a] + pm[a];
            #pragma unroll 8
            for (int c = 0; c < 32; c++) s += wlocT[c * 129 + a] * fi[c];
            part += tanhf(s) * v_att[a];
        }
        part = warp_sum(part);
        if (lane == 0) e_s[i] = (i < len) ? part : -1e9f;
    }
    __syncthreads();

    // softmax over 200
    float e = (tid < TENC) ? e_s[tid] : -1e30f;
    float m = warp_max(e);
    if (lane == 0) red16[warp] = m;
    __syncthreads();
    if (tid == 0) {
        float mm = red16[0];
        #pragma unroll
        for (int i = 1; i < 16; i++) mm = fmaxf(mm, red16[i]);
        red16[0] = mm;
    }
    __syncthreads();
    float mx = red16[0];
    __syncthreads();
    float ex = (tid < TENC) ? __expf(e - mx) : 0.f;
    float ssum = warp_sum(ex);
    if (lane == 0) red16[warp] = ssum;
    __syncthreads();
    if (tid == 0) {
        float tot = 0.f;
        #pragma unroll
        for (int i = 0; i < 16; i++) tot += red16[i];
        red16[0] = tot;
    }
    __syncthreads();
    float inv = 1.f / red16[0];
    if (tid < TENC) {
        float w = ex * inv;
        e_s[tid] = w;
        g_wprev[b * TENC + tid] = w;
        g_wcum[b * TENC + tid] = wc_s[tid] + w;
        align_out[((size_t)b * TDEC + t) * TENC + tid] = w;
    }
    __syncthreads();

    // context[b] = sum_i w[i] enc[b,i,:]
    if (tid < 256) {
        int col = tid & 127, half = tid >> 7;
        const float4* encb = (const float4*)(enc + (size_t)b * TENC * E_) + col;
        float4 acc = make_float4(0.f, 0.f, 0.f, 0.f);
        #pragma unroll 4
        for (int i = half * 100; i < half * 100 + 100; i++) {
            float w = e_s[i];
            float4 v = encb[(size_t)i * 128];
            acc.x += w * v.x; acc.y += w * v.y; acc.z += w * v.z; acc.w += w * v.w;
        }
        ((float4*)feat)[tid] = acc;
    }
    __syncthreads();
    if (tid < 128) {
        float4 a0 = ((float4*)feat)[tid];
        float4 a1 = ((float4*)feat)[tid + 128];
        float4 r = make_float4(a0.x + a1.x, a0.y + a1.y, a0.z + a1.z, a0.w + a1.w);
        ((float4*)(g_ctx[t & 1] + b * E_))[tid] = r;
    }
    __syncthreads();
}

// ---------------- gen pointwise + frame/stop for step tt ----------------
__device__ void genpw_frame(int b, int tt, float* pool,
                            const float* __restrict__ gb,
                            const float* __restrict__ fW, const float* __restrict__ fb,
                            const float* __restrict__ sW, const float* __restrict__ sb,
                            float* __restrict__ spec, float* __restrict__ stop) {
    const int tid = threadIdx.x;
    const int warp = tid >> 5, lane = tid & 31;
    float* proto = pool;  // [1536] = h_gen(1024) | ctx(512)

    const float* gg = g_ggen + (size_t)b * (4 * D_);
    for (int d = tid; d < D_; d += NTHR) {
        float gi = gg[d]           + gb[d];
        float gf = gg[D_ + d]      + gb[D_ + d];
        float gc = gg[2 * D_ + d]  + gb[2 * D_ + d];
        float go = gg[3 * D_ + d]  + gb[3 * D_ + d];
        float c = sigf(gf) * g_cgen[b * D_ + d] + sigf(gi) * tanhf(gc);
        float h = sigf(go) * tanhf(c);
        g_cgen[b * D_ + d] = c;
        g_hgen[b * D_ + d] = h;
        proto[d] = h;
    }
    const float* cx = g_ctx[tt & 1] + b * E_;
    for (int k = tid; k < E_; k += NTHR) proto[D_ + k] = cx[k];
    __syncthreads();

    for (int r = warp; r < M_ + 1; r += 16) {
        const float* w = (r < M_) ? (fW + (size_t)r * (D_ + E_)) : sW;
        float acc = 0.f;
        for (int k = lane * 4; k < D_ + E_; k += 128) {
            float4 w4 = *(const float4*)(w + k);
            float4 x4 = *(const float4*)(proto + k);
            acc += w4.x * x4.x + w4.y * x4.y + w4.z * x4.z + w4.w * x4.w;
        }
        acc = warp_sum(acc);
        if (lane == 0) {
            if (r < M_) spec[((size_t)b * TDEC + tt) * M_ + r] = acc + fb[r];
            else        stop[(size_t)b * TDEC + tt] = acc + sb[0];
        }
    }
    __syncthreads();
}

// ---------------- the persistent decoder ----------------
__global__ void __launch_bounds__(NTHR, 1)
decoder_kernel(const float* __restrict__ enc, const int* __restrict__ lens,
               const float* __restrict__ aWih, const float* __restrict__ aWhh, const float* __restrict__ ab,
               const float* __restrict__ gWih, const float* __restrict__ gWhh, const float* __restrict__ gb,
               const float* __restrict__ Wq, const float* __restrict__ lk,
               const float* __restrict__ Wloc, const float* __restrict__ v_att, const float* __restrict__ b_att,
               const float* __restrict__ fW, const float* __restrict__ fb,
               const float* __restrict__ sW, const float* __restrict__ sb,
               float* __restrict__ spec, float* __restrict__ stop, float* __restrict__ align_out) {
    extern __shared__ __align__(16) float pool[];
    const int blk = blockIdx.x;
    unsigned ls = g_sense;

    for (int t = 0; t < TDEC; t++) {
        // Phase A: att-LSTM gates. x = [pre_t(256) | ctx_{t-1}(512)], h = h_att
        lstm_gates(aWih, aWhh, P_ + E_,
                   g_pre + (size_t)t * P_, P_, TDEC * P_,
                   g_ctx[(t + 1) & 1], E_, E_,
                   g_hatt, D_,
                   g_gatt, pool, blk);
        grid_bar(ls);
        // Phase B
        if (blk < 32) {
            attention_step(blk, t, pool, ab, Wq, lk, Wloc, v_att, b_att, lens, enc, align_out);
        } else if (blk < 64 && t > 0) {
            genpw_frame(blk - 32, t - 1, pool, gb, fW, fb, sW, sb, spec, stop);
        }
        grid_bar(ls);
        // Phase C: gen-LSTM gates. x = [h_att(1024) | ctx_t(512)], h = h_gen
        lstm_gates(gWih, gWhh, D_ + E_,
                   g_hatt, D_, D_,
                   g_ctx[t & 1], E_, E_,
                   g_hgen, D_,
                   g_ggen, pool, blk);
    }
    grid_bar(ls);
    if (blk >= 32 && blk < 64) {
        genpw_frame(blk - 32, TDEC - 1, pool, gb, fW, fb, sW, sb, spec, stop);
    }
}

// ---------------- prologue kernels ----------------
__global__ void init_kernel() {
    int i = blockIdx.x * blockDim.x + threadIdx.x;   // 128*256 = 32768
    if (i < B_ * D_) { g_hatt[i] = 0.f; g_catt[i] = 0.f; g_hgen[i] = 0.f; g_cgen[i] = 0.f; }
    if (i < B_ * E_) { g_ctx[0][i] = 0.f; g_ctx[1][i] = 0.f; }
    if (i < B_ * TENC) { g_wprev[i] = 0.f; g_wcum[i] = 0.f; }
}

// warp-per-output prenet: coalesced weight reads
__global__ void prenet_kernel(const float* __restrict__ target,
                              const float* __restrict__ W1, const float* __restrict__ b1,
                              const float* __restrict__ W2, const float* __restrict__ b2) {
    int bt = blockIdx.x;
    int b = bt / TDEC, t = bt % TDEC;
    __shared__ float st[M_];
    __shared__ float sx1[P_];
    int tid = threadIdx.x;  // 256, 8 warps
    int warp = tid >> 5, lane = tid & 31;
    if (tid < M_) st[tid] = (t == 0) ? 0.f : target[((size_t)b * M_ + tid) * TDEC + (t - 1)];
    __syncthreads();
    // layer 1: warp per p (32 p's each), lane over m (80 = 32+32+16)
    for (int j = 0; j < 32; j++) {
        int p = warp * 32 + j;
        const float* w = W1 + (size_t)p * M_;
        float acc = w[lane] * st[lane] + w[lane + 32] * st[lane + 32];
        if (lane < 16) acc += w[lane + 64] * st[lane + 64];
        acc = warp_sum(acc);
        if (lane == 0) sx1[p] = fmaxf(acc + b1[p], 0.f);
    }
    __syncthreads();
    // layer 2: warp per p, lane over k (256 = 8x32)
    for (int j = 0; j < 32; j++) {
        int p = warp * 32 + j;
        const float* w = W2 + (size_t)p * P_;
        float acc = 0.f;
        #pragma unroll
        for (int q = 0; q < 8; q++) acc += w[lane + 32 * q] * sx1[lane + 32 * q];
        acc = warp_sum(acc);
        if (lane == 0) g_pre[((size_t)b * TDEC + t) * P_ + p] = fmaxf(acc + b2[p], 0.f);
    }
}

// warp-per-output procmem: coalesced Wm reads
__global__ void procmem_kernel(const float* __restrict__ enc, const float* __restrict__ Wm) {
    int i = blockIdx.x, b = blockIdx.y;
    __shared__ __align__(16) float se[E_];
    int tid = threadIdx.x;  // 128, 4 warps
    int warp = tid >> 5, lane = tid & 31;
    for (int k = tid; k < E_; k += 128) se[k] = enc[((size_t)b * TENC + i) * E_ + k];
    __syncthreads();
    const float4* se4 = (const float4*)se;
    for (int j = 0; j < 32; j++) {
        int a = warp * 32 + j;
        const float4* w4 = (const float4*)(Wm + (size_t)a * E_);
        float acc = 0.f;
        #pragma unroll
        for (int q = 0; q < 4; q++) {
            float4 w = w4[lane + 32 * q];
            float4 x = se4[lane + 32 * q];
            acc += w.x * x.x + w.y * x.y + w.z * x.z + w.w * x.w;
        }
        acc = warp_sum(acc);
        if (lane == 0) g_pm[((size_t)b * TENC + i) * A_ + a] = acc;
    }
}

// ---------------- launch ----------------
extern "C" void kernel_launch(void* const* d_in, const int* in_sizes, int n_in,
                              void* d_out, int out_size) {
    const float* enc    = (const float*)d_in[0];
    const int*   lens   = (const int*)d_in[1];
    const float* target = (const float*)d_in[2];
    // d_in[3] = teacher_forcing_ratio (==1; fully teacher-forced, unused)
    const float* pW1 = (const float*)d_in[4];
    const float* pb1 = (const float*)d_in[5];
    const float* pW2 = (const float*)d_in[6];
    const float* pb2 = (const float*)d_in[7];
    const float* aWih = (const float*)d_in[8];
    const float* aWhh = (const float*)d_in[9];
    const float* ab   = (const float*)d_in[10];
    const float* gWih = (const float*)d_in[11];
    const float* gWhh = (const float*)d_in[12];
    const float* gb   = (const float*)d_in[13];
    const float* Wq   = (const float*)d_in[14];
    const float* Wm   = (const float*)d_in[15];
    const float* lk   = (const float*)d_in[16];
    const float* Wloc = (const float*)d_in[17];
    const float* v_att = (const float*)d_in[18];
    const float* b_att = (const float*)d_in[19];
    const float* fW = (const float*)d_in[20];
    const float* fb = (const float*)d_in[21];
    const float* sW = (const float*)d_in[22];
    const float* sb = (const float*)d_in[23];

    float* out  = (float*)d_out;
    float* spec  = out;                                    // [B, Tdec, M]
    float* stop  = out + (size_t)B_ * TDEC * M_;           // [B, Tdec]
    float* align = stop + (size_t)B_ * TDEC;               // [B, Tdec, Tenc]

    // dynamic smem: 2x(32*132) W + 2x(32*132) x + 8x(32*33) reduce = 25344 floats
    const int smem_bytes = 25344 * 4;
    static int configured = 0;
    if (!configured) {
        cudaFuncSetAttribute(decoder_kernel, cudaFuncAttributeMaxDynamicSharedMemorySize, smem_bytes);
        configured = 1;
    }

    init_kernel<<<128, 256>>>();
    prenet_kernel<<<B_ * TDEC, 256>>>(target, pW1, pb1, pW2, pb2);
    procmem_kernel<<<dim3(TENC, B_), 128>>>(enc, Wm);

    decoder_kernel<<<NBLK, NTHR, smem_bytes>>>(enc, lens,
                                               aWih, aWhh, ab, gWih, gWhh, gb,
                                               Wq, lk, Wloc, v_att, b_att,
                                               fW, fb, sW, sb,
                                               spec, stop, align);
}

// round 5
// speedup vs baseline: 7.4315x; 1.8562x over previous
#include <cuda_runtime.h>
#include <math.h>

#define B_    32
#define TENC  200
#define E_    512
#define D_    1024
#define P_    256
#define M_    80
#define TDEC  600
#define A_    128
#define LF_   32
#define KW_   31
#define PADW  15
#define NBLK  128
#define NTHR  512
#define CHUNK 128
#define WPAD  132                 // padded chunk stride in floats (16B-aligned)
#define BUFFL (2 * 32 * WPAD)     // floats per (w,x) buffer = 8448
#define REDOFF (3 * BUFFL)        // 25344
#define POOLFL (REDOFF + 8448)    // 33792 floats = 135168 B

// ---------------- device scratch (static, allocation-free) ----------------
__device__ __align__(16) float g_pre[(size_t)B_ * TDEC * P_];
__device__ __align__(16) float g_pm[(size_t)B_ * TENC * A_];
__device__ __align__(16) float g_lp[(size_t)B_ * TENC * A_];     // location proj per step
__device__ __align__(16) float g_hatt[B_ * D_];
__device__ __align__(16) float g_catt[B_ * D_];
__device__ __align__(16) float g_hgen[B_ * D_];
__device__ __align__(16) float g_cgen[B_ * D_];
__device__ __align__(16) float g_ctx[2][B_ * E_];
__device__ __align__(16) float g_wprev[B_ * TENC];
__device__ __align__(16) float g_wcum[B_ * TENC];
__device__ __align__(16) float g_gatt[(size_t)B_ * 4 * D_];
__device__ __align__(16) float g_ggen[(size_t)B_ * 4 * D_];

// ---------------- grid barrier ----------------
__device__ unsigned g_count = 0;
__device__ volatile unsigned g_sense = 0;

__device__ __forceinline__ void grid_bar(unsigned& ls) {
    __syncthreads();
    ls ^= 1u;
    if (threadIdx.x == 0) {
        __threadfence();
        unsigned old = atomicAdd(&g_count, 1u);
        if (old == NBLK - 1) {
            atomicExch(&g_count, 0u);
            __threadfence();
            g_sense = ls;
        } else {
            while (g_sense != ls) { __nanosleep(32); }
            __threadfence();
        }
    }
    __syncthreads();
}

// ---------------- helpers ----------------
__device__ __forceinline__ float warp_sum(float v) {
    v += __shfl_xor_sync(0xffffffffu, v, 16);
    v += __shfl_xor_sync(0xffffffffu, v, 8);
    v += __shfl_xor_sync(0xffffffffu, v, 4);
    v += __shfl_xor_sync(0xffffffffu, v, 2);
    v += __shfl_xor_sync(0xffffffffu, v, 1);
    return v;
}
__device__ __forceinline__ float warp_max(float v) {
    v = fmaxf(v, __shfl_xor_sync(0xffffffffu, v, 16));
    v = fmaxf(v, __shfl_xor_sync(0xffffffffu, v, 8));
    v = fmaxf(v, __shfl_xor_sync(0xffffffffu, v, 4));
    v = fmaxf(v, __shfl_xor_sync(0xffffffffu, v, 2));
    v = fmaxf(v, __shfl_xor_sync(0xffffffffu, v, 1));
    return v;
}
__device__ __forceinline__ float sigf(float x) { return 1.f / (1.f + __expf(-x)); }

__device__ __forceinline__ void cp16(float* smem_dst, const float* gsrc) {
    unsigned s = (unsigned)__cvta_generic_to_shared(smem_dst);
    asm volatile("cp.async.cg.shared.global [%0], [%1], 16;" :: "r"(s), "l"(gsrc));
}
__device__ __forceinline__ void cp_commit() { asm volatile("cp.async.commit_group;"); }
__device__ __forceinline__ void cp_wait1() { asm volatile("cp.async.wait_group 1;"); }
__device__ __forceinline__ void cp_wait0() { asm volatile("cp.async.wait_group 0;"); }

typedef unsigned long long ull;
__device__ __forceinline__ ull pk(float lo, float hi) {
    ull r; asm("mov.b64 %0, {%1, %2};" : "=l"(r) : "f"(lo), "f"(hi)); return r;
}
__device__ __forceinline__ float2 upk(ull v) {
    float2 f; asm("mov.b64 {%0, %1}, %2;" : "=f"(f.x), "=f"(f.y) : "l"(v)); return f;
}
__device__ __forceinline__ void fma2(ull& acc, ull a, ull b) {
    asm("fma.rn.f32x2 %0, %1, %2, %0;" : "+l"(acc) : "l"(a), "l"(b));
}
__device__ __forceinline__ void lds_2x64(ull& a, ull& b, unsigned saddr) {
    asm volatile("ld.shared.v2.b64 {%0, %1}, [%2];" : "=l"(a), "=l"(b) : "r"(saddr));
}
__device__ __forceinline__ unsigned sptr(const void* p) {
    return (unsigned)__cvta_generic_to_shared(p);
}

// ---------------- LSTM gate GEMM: gates[b][4096 rows], FFMA2, triple-buffered ----------------
__device__ void lstm_gates(const float* __restrict__ Wih, const float* __restrict__ Whh,
                           int KX,
                           const float* s0, int l0, int st0,
                           const float* s1, int l1, int st1,
                           const float* s2, int st2,
                           float* __restrict__ gates_out, float* pool, int blk) {
    const int KTOT = KX + D_;
    const int NCH = KTOT / CHUNK;
    const int rowbase = blk * 32;
    const int tid = threadIdx.x;
    const int kg = tid >> 6;
    const int rg = (tid >> 3) & 7;
    const int bg = tid & 7;

    const unsigned pool_sa = sptr(pool);
    float* red = pool + REDOFF;

    const int i0 = tid, i1 = tid + NTHR;
    const int wr0 = i0 >> 5, wc0 = (i0 & 31) * 4;
    const int wr1 = i1 >> 5, wc1 = (i1 & 31) * 4;

    #define STAGE(buf_, tb_)  do {                                               \
        int tb = (tb_);                                                           \
        float* wb = pool + (buf_) * BUFFL;                                         \
        float* xb = wb + 32 * WPAD;                                                \
        {                                                                          \
            int k = tb + wc0;                                                      \
            const float* src = (k < KX) ? Wih + (size_t)(rowbase + wr0) * KX + k   \
                                        : Whh + (size_t)(rowbase + wr0) * D_ + (k - KX); \
            cp16(wb + wr0 * WPAD + wc0, src);                                      \
        }                                                                          \
        {                                                                          \
            int k = tb + wc1;                                                      \
            const float* src = (k < KX) ? Wih + (size_t)(rowbase + wr1) * KX + k   \
                                        : Whh + (size_t)(rowbase + wr1) * D_ + (k - KX); \
            cp16(wb + wr1 * WPAD + wc1, src);                                      \
        }                                                                          \
        {                                                                          \
            int k = tb + wc0;                                                      \
            const float* src;                                                      \
            if (k < l0)           src = s0 + (size_t)wr0 * st0 + k;                \
            else if (k < l0 + l1) src = s1 + (size_t)wr0 * st1 + (k - l0);         \
            else                  src = s2 + (size_t)wr0 * st2 + (k - l0 - l1);    \
            cp16(xb + wr0 * WPAD + wc0, src);                                      \
        }                                                                          \
        {                                                                          \
            int k = tb + wc1;                                                      \
            const float* src;                                                      \
            if (k < l0)           src = s0 + (size_t)wr1 * st0 + k;                \
            else if (k < l0 + l1) src = s1 + (size_t)wr1 * st1 + (k - l0);         \
            else                  src = s2 + (size_t)wr1 * st2 + (k - l0 - l1);    \
            cp16(xb + wr1 * WPAD + wc1, src);                                      \
        }                                                                          \
    } while (0)

    ull acc[4][4];
    #pragma unroll
    for (int i = 0; i < 4; i++)
        #pragma unroll
        for (int j = 0; j < 4; j++) acc[i][j] = 0ull;

    STAGE(0, 0); cp_commit();
    STAGE(1, CHUNK); cp_commit();

    int bi = 0, si = 2;
    for (int c = 0; c < NCH; c++) {
        if (c + 1 < NCH) cp_wait1(); else cp_wait0();
        __syncthreads();
        if (c + 2 < NCH) { STAGE(si, (c + 2) * CHUNK); cp_commit(); }

        const unsigned wbase = pool_sa + (unsigned)(bi * BUFFL + rg * WPAD + kg * 16) * 4u;
        const unsigned xbase = pool_sa + (unsigned)(bi * BUFFL + 32 * WPAD + bg * WPAD + kg * 16) * 4u;
        #pragma unroll
        for (int kk = 0; kk < 4; kk++) {
            ull w[8], x[8];
            lds_2x64(w[0], w[1], wbase + kk * 16);
            lds_2x64(w[2], w[3], wbase + 8 * WPAD * 4 + kk * 16);
            lds_2x64(w[4], w[5], wbase + 16 * WPAD * 4 + kk * 16);
            lds_2x64(w[6], w[7], wbase + 24 * WPAD * 4 + kk * 16);
            lds_2x64(x[0], x[1], xbase + kk * 16);
            lds_2x64(x[2], x[3], xbase + 8 * WPAD * 4 + kk * 16);
            lds_2x64(x[4], x[5], xbase + 16 * WPAD * 4 + kk * 16);
            lds_2x64(x[6], x[7], xbase + 24 * WPAD * 4 + kk * 16);
            #pragma unroll
            for (int i = 0; i < 4; i++)
                #pragma unroll
                for (int j = 0; j < 4; j++) {
                    fma2(acc[i][j], w[2 * i],     x[2 * j]);
                    fma2(acc[i][j], w[2 * i + 1], x[2 * j + 1]);
                }
        }
        bi = (bi == 2) ? 0 : bi + 1;
        si = (si == 2) ? 0 : si + 1;
    }
    #undef STAGE

    __syncthreads();   // protect red region (aliases buffers not in use? red is separate) / order
    #pragma unroll
    for (int i = 0; i < 4; i++)
        #pragma unroll
        for (int j = 0; j < 4; j++) {
            float2 f = upk(acc[i][j]);
            red[kg * (32 * 33) + (rg + 8 * i) * 33 + (bg + 8 * j)] = f.x + f.y;
        }
    __syncthreads();
    for (int p = tid; p < 1024; p += NTHR) {
        int b = p >> 5, r = p & 31;
        float s = 0.f;
        #pragma unroll
        for (int q = 0; q < 8; q++) s += red[q * (32 * 33) + r * 33 + b];
        gates_out[(size_t)b * (4 * D_) + rowbase + r] = s;
    }
    __syncthreads();
}

// ---------------- B1 (blocks 0-31): att pointwise + query ----------------
__device__ void att_pw_query(int b, float* pool,
                             const float* __restrict__ ab,
                             const float* __restrict__ Wq,
                             const float* __restrict__ b_att,
                             const float* __restrict__ v_att) {
    const int tid = threadIdx.x;
    const int warp = tid >> 5, lane = tid & 31;
    float* h_s = pool;           // 1024
    float* q_s = pool + 1024;    // 128
    float* v_s = pool + 1152;    // 128

    const float* gat = g_gatt + (size_t)b * (4 * D_);
    for (int d = tid; d < D_; d += NTHR) {
        float gi = gat[d]          + ab[d];
        float gf = gat[D_ + d]     + ab[D_ + d];
        float gc = gat[2 * D_ + d] + ab[2 * D_ + d];
        float go = gat[3 * D_ + d] + ab[3 * D_ + d];
        float c = sigf(gf) * g_catt[b * D_ + d] + sigf(gi) * tanhf(gc);
        float h = sigf(go) * tanhf(c);
        g_catt[b * D_ + d] = c;
        g_hatt[b * D_ + d] = h;
        h_s[d] = h;
    }
    if (tid < A_) v_s[tid] = v_att[tid];
    __syncthreads();

    const float4* h4 = (const float4*)h_s;
    for (int a = warp * 8; a < warp * 8 + 8; a++) {
        const float4* wq = (const float4*)(Wq + (size_t)a * D_);
        float acc = 0.f;
        #pragma unroll
        for (int kk = 0; kk < 8; kk++) {
            float4 w4 = wq[lane + 32 * kk];
            float4 x4 = h4[lane + 32 * kk];
            acc += w4.x * x4.x + w4.y * x4.y + w4.z * x4.z + w4.w * x4.w;
        }
        acc = warp_sum(acc);
        if (lane == 0) q_s[a] = acc + b_att[a];
    }
    __syncthreads();
}

// ---------------- B1 (blocks 32-127): conv + locproj for (b, third) ----------------
__device__ void conv_locproj(int b, int third, float* pool,
                             const float* __restrict__ lk,
                             const float* __restrict__ Wloc) {
    const int tid = threadIdx.x;
    const int lo = third * 67;
    const int n = (third == 2) ? 66 : 67;

    float* wp_s  = pool;          // 104
    float* wc_s  = pool + 104;    // 104
    float* lkT   = pool + 208;    // 62*33 = 2046
    float* wlocT = pool + 2256;   // 32*129 = 4128
    float* feat  = pool + 6400;   // 67*36 = 2412  (16B-aligned: 6400*4)

    for (int idx = tid; idx < 104; idx += NTHR) {
        int j = lo - 15 + idx;
        bool ok = (j >= 0 && j < TENC);
        wp_s[idx] = ok ? g_wprev[b * TENC + j] : 0.f;
        wc_s[idx] = ok ? g_wcum[b * TENC + j] : 0.f;
    }
    for (int idx = tid; idx < 62 * 32; idx += NTHR) {
        int tap = idx >> 5, c = idx & 31;
        lkT[tap * 33 + c] = lk[c * 62 + tap];
    }
    for (int idx = tid; idx < A_ * LF_; idx += NTHR) {
        int a = idx >> 5, c = idx & 31;
        wlocT[c * 129 + a] = Wloc[idx];
    }
    __syncthreads();

    // conv with sliding window: thread = (c, iq), 4 outputs each, 2 passes
    {
        int c = tid & 31, iq = tid >> 5;   // iq 0..15
        for (int p = 0; p < 2; p++) {
            int ig4 = p * 64 + iq * 4;
            if (ig4 < n) {
                float f0 = 0.f, f1 = 0.f, f2 = 0.f, f3 = 0.f;
                {
                    float a0 = wp_s[ig4], a1 = wp_s[ig4 + 1], a2 = wp_s[ig4 + 2], a3 = wp_s[ig4 + 3];
                    #pragma unroll
                    for (int k = 0; k < KW_; k++) {
                        float lkv = lkT[k * 33 + c];
                        f0 += lkv * a0; f1 += lkv * a1; f2 += lkv * a2; f3 += lkv * a3;
                        a0 = a1; a1 = a2; a2 = a3; a3 = wp_s[ig4 + k + 4];
                    }
                }
                {
                    float a0 = wc_s[ig4], a1 = wc_s[ig4 + 1], a2 = wc_s[ig4 + 2], a3 = wc_s[ig4 + 3];
                    #pragma unroll
                    for (int k = 0; k < KW_; k++) {
                        float lkv = lkT[(KW_ + k) * 33 + c];
                        f0 += lkv * a0; f1 += lkv * a1; f2 += lkv * a2; f3 += lkv * a3;
                        a0 = a1; a1 = a2; a2 = a3; a3 = wc_s[ig4 + k + 4];
                    }
                }
                if (ig4 + 0 < n) feat[(ig4 + 0) * 36 + c] = f0;
                if (ig4 + 1 < n) feat[(ig4 + 1) * 36 + c] = f1;
                if (ig4 + 2 < n) feat[(ig4 + 2) * 36 + c] = f2;
                if (ig4 + 3 < n) feat[(ig4 + 3) * 36 + c] = f3;
            }
        }
    }
    __syncthreads();

    // locproj: lp[i][a] = sum_c wloc[a][c] * feat[i][c]; thread = (a, ig2)
    {
        int a = tid & 127, ig2 = tid >> 7;   // ig2 0..3
        ull wl[16];
        #pragma unroll
        for (int p4 = 0; p4 < 8; p4++) {
            wl[2 * p4]     = pk(wlocT[(4 * p4) * 129 + a],     wlocT[(4 * p4 + 1) * 129 + a]);
            wl[2 * p4 + 1] = pk(wlocT[(4 * p4 + 2) * 129 + a], wlocT[(4 * p4 + 3) * 129 + a]);
        }
        unsigned feat_sa = sptr(feat);
        for (int ii = ig2; ii < n; ii += 4) {
            ull acc = 0ull;
            unsigned base = feat_sa + (unsigned)ii * 144u;
            #pragma unroll
            for (int p4 = 0; p4 < 8; p4++) {
                ull f0, f1;
                lds_2x64(f0, f1, base + p4 * 16);
                fma2(acc, wl[2 * p4], f0);
                fma2(acc, wl[2 * p4 + 1], f1);
            }
            float2 f = upk(acc);
            g_lp[((size_t)b * TENC + lo + ii) * A_ + a] = f.x + f.y;
        }
    }
    __syncthreads();
}

// ---------------- B2 (blocks 0-31): energy + softmax + context ----------------
__device__ void energy_softmax_ctx(int b, int t, float* pool,
                                   const int* __restrict__ lens,
                                   const float* __restrict__ enc,
                                   float* __restrict__ align_out) {
    const int tid = threadIdx.x;
    const int warp = tid >> 5, lane = tid & 31;
    float* q_s   = pool + 1024;   // from B1
    float* v_s   = pool + 1152;   // from B1
    float* e_s   = pool + 1280;   // 224
    float* red16 = pool + 1504;   // 16
    float* cpart = pool + 1536;   // 1024

    int len = lens[b];
    for (int i = warp; i < TENC; i += 16) {
        const float* lp = g_lp + ((size_t)b * TENC + i) * A_;
        const float* pm = g_pm + ((size_t)b * TENC + i) * A_;
        float part = 0.f;
        #pragma unroll
        for (int aa = 0; aa < 4; aa++) {
            int a = aa * 32 + lane;
            part += tanhf(q_s[a] + pm[a] + lp[a]) * v_s[a];
        }
        part = warp_sum(part);
        if (lane == 0) e_s[i] = (i < len) ? part : -1e9f;
    }
    __syncthreads();

    float e = (tid < TENC) ? e_s[tid] : -1e30f;
    float m = warp_max(e);
    if (lane == 0) red16[warp] = m;
    __syncthreads();
    if (tid == 0) {
        float mm = red16[0];
        #pragma unroll
        for (int i = 1; i < 16; i++) mm = fmaxf(mm, red16[i]);
        red16[0] = mm;
    }
    __syncthreads();
    float mx = red16[0];
    __syncthreads();
    float ex = (tid < TENC) ? __expf(e - mx) : 0.f;
    float ssum = warp_sum(ex);
    if (lane == 0) red16[warp] = ssum;
    __syncthreads();
    if (tid == 0) {
        float tot = 0.f;
        #pragma unroll
        for (int i = 0; i < 16; i++) tot += red16[i];
        red16[0] = tot;
    }
    __syncthreads();
    float inv = 1.f / red16[0];
    if (tid < TENC) {
        float w = ex * inv;
        e_s[tid] = w;
        g_wprev[b * TENC + tid] = w;
        g_wcum[b * TENC + tid] += w;
        align_out[((size_t)b * TDEC + t) * TENC + tid] = w;
    }
    __syncthreads();

    if (tid < 256) {
        int col = tid & 127, half = tid >> 7;
        const float4* encb = (const float4*)(enc + (size_t)b * TENC * E_) + col;
        float4 acc = make_float4(0.f, 0.f, 0.f, 0.f);
        #pragma unroll 4
        for (int i = half * 100; i < half * 100 + 100; i++) {
            float w = e_s[i];
            float4 v = encb[(size_t)i * 128];
            acc.x += w * v.x; acc.y += w * v.y; acc.z += w * v.z; acc.w += w * v.w;
        }
        ((float4*)cpart)[tid] = acc;
    }
    __syncthreads();
    if (tid < 128) {
        float4 a0 = ((float4*)cpart)[tid];
        float4 a1 = ((float4*)cpart)[tid + 128];
        float4 r = make_float4(a0.x + a1.x, a0.y + a1.y, a0.z + a1.z, a0.w + a1.w);
        ((float4*)(g_ctx[t & 1] + b * E_))[tid] = r;
    }
    __syncthreads();
}

// ---------------- gen pointwise + frame/stop for step tt ----------------
__device__ void genpw_frame(int b, int tt, float* pool,
                            const float* __restrict__ gb,
                            const float* __restrict__ fW, const float* __restrict__ fb,
                            const float* __restrict__ sW, const float* __restrict__ sb,
                            float* __restrict__ spec, float* __restrict__ stop) {
    const int tid = threadIdx.x;
    const int warp = tid >> 5, lane = tid & 31;
    float* proto = pool;  // 1536

    const float* gg = g_ggen + (size_t)b * (4 * D_);
    for (int d = tid; d < D_; d += NTHR) {
        float gi = gg[d]          + gb[d];
        float gf = gg[D_ + d]     + gb[D_ + d];
        float gc = gg[2 * D_ + d] + gb[2 * D_ + d];
        float go = gg[3 * D_ + d] + gb[3 * D_ + d];
        float c = sigf(gf) * g_cgen[b * D_ + d] + sigf(gi) * tanhf(gc);
        float h = sigf(go) * tanhf(c);
        g_cgen[b * D_ + d] = c;
        g_hgen[b * D_ + d] = h;
        proto[d] = h;
    }
    const float* cx = g_ctx[tt & 1] + b * E_;
    for (int k = tid; k < E_; k += NTHR) proto[D_ + k] = cx[k];
    __syncthreads();

    for (int r = warp; r < M_ + 1; r += 16) {
        const float* w = (r < M_) ? (fW + (size_t)r * (D_ + E_)) : sW;
        float acc = 0.f;
        for (int k = lane * 4; k < D_ + E_; k += 128) {
            float4 w4 = *(const float4*)(w + k);
            float4 x4 = *(const float4*)(proto + k);
            acc += w4.x * x4.x + w4.y * x4.y + w4.z * x4.z + w4.w * x4.w;
        }
        acc = warp_sum(acc);
        if (lane == 0) {
            if (r < M_) spec[((size_t)b * TDEC + tt) * M_ + r] = acc + fb[r];
            else        stop[(size_t)b * TDEC + tt] = acc + sb[0];
        }
    }
    __syncthreads();
}

// ---------------- the persistent decoder ----------------
__global__ void __launch_bounds__(NTHR, 1)
decoder_kernel(const float* __restrict__ enc, const int* __restrict__ lens,
               const float* __restrict__ aWih, const float* __restrict__ aWhh, const float* __restrict__ ab,
               const float* __restrict__ gWih, const float* __restrict__ gWhh, const float* __restrict__ gb,
               const float* __restrict__ Wq, const float* __restrict__ lk,
               const float* __restrict__ Wloc, const float* __restrict__ v_att, const float* __restrict__ b_att,
               const float* __restrict__ fW, const float* __restrict__ fb,
               const float* __restrict__ sW, const float* __restrict__ sb,
               float* __restrict__ spec, float* __restrict__ stop, float* __restrict__ align_out) {
    extern __shared__ __align__(16) float pool[];
    const int blk = blockIdx.x;
    unsigned ls = g_sense;

    for (int t = 0; t < TDEC; t++) {
        // Phase A: att-LSTM gates. x = [pre_t | ctx_{t-1}], h = h_att^{t-1}
        lstm_gates(aWih, aWhh, P_ + E_,
                   g_pre + (size_t)t * P_, P_, TDEC * P_,
                   g_ctx[(t + 1) & 1], E_, E_,
                   g_hatt, D_,
                   g_gatt, pool, blk);
        grid_bar(ls);
        // Phase B1: pointwise+query (0-31) || conv+locproj (32-127)
        if (blk < 32) {
            att_pw_query(blk, pool, ab, Wq, b_att, v_att);
        } else {
            int cb = blk - 32;
            conv_locproj(cb & 31, cb >> 5, pool, lk, Wloc);
        }
        grid_bar(ls);
        // Phase B2: energy/softmax/context (0-31) || frame of t-1 (32-63)
        if (blk < 32) {
            energy_softmax_ctx(blk, t, pool, lens, enc, align_out);
        } else if (blk < 64 && t > 0) {
            genpw_frame(blk - 32, t - 1, pool, gb, fW, fb, sW, sb, spec, stop);
        }
        grid_bar(ls);
        // Phase C: gen-LSTM gates. x = [h_att | ctx_t], h = h_gen^{t-1}
        lstm_gates(gWih, gWhh, D_ + E_,
                   g_hatt, D_, D_,
                   g_ctx[t & 1], E_, E_,
                   g_hgen, D_,
                   g_ggen, pool, blk);
    }
    grid_bar(ls);
    if (blk >= 32 && blk < 64) {
        genpw_frame(blk - 32, TDEC - 1, pool, gb, fW, fb, sW, sb, spec, stop);
    }
}

// ---------------- prologue kernels ----------------
__global__ void init_kernel() {
    int i = blockIdx.x * blockDim.x + threadIdx.x;
    if (i < B_ * D_) { g_hatt[i] = 0.f; g_catt[i] = 0.f; g_hgen[i] = 0.f; g_cgen[i] = 0.f; }
    if (i < B_ * E_) { g_ctx[0][i] = 0.f; g_ctx[1][i] = 0.f; }
    if (i < B_ * TENC) { g_wprev[i] = 0.f; g_wcum[i] = 0.f; }
}

__global__ void prenet_kernel(const float* __restrict__ target,
                              const float* __restrict__ W1, const float* __restrict__ b1,
                              const float* __restrict__ W2, const float* __restrict__ b2) {
    int bt = blockIdx.x;
    int b = bt / TDEC, t = bt % TDEC;
    __shared__ float st[M_];
    __shared__ float sx1[P_];
    int tid = threadIdx.x;  // 256
    int warp = tid >> 5, lane = tid & 31;
    if (tid < M_) st[tid] = (t == 0) ? 0.f : target[((size_t)b * M_ + tid) * TDEC + (t - 1)];
    __syncthreads();
    for (int j = 0; j < 32; j++) {
        int p = warp * 32 + j;
        const float* w = W1 + (size_t)p * M_;
        float acc = w[lane] * st[lane] + w[lane + 32] * st[lane + 32];
        if (lane < 16) acc += w[lane + 64] * st[lane + 64];
        acc = warp_sum(acc);
        if (lane == 0) sx1[p] = fmaxf(acc + b1[p], 0.f);
    }
    __syncthreads();
    for (int j = 0; j < 32; j++) {
        int p = warp * 32 + j;
        const float* w = W2 + (size_t)p * P_;
        float acc = 0.f;
        #pragma unroll
        for (int q = 0; q < 8; q++) acc += w[lane + 32 * q] * sx1[lane + 32 * q];
        acc = warp_sum(acc);
        if (lane == 0) g_pre[((size_t)b * TDEC + t) * P_ + p] = fmaxf(acc + b2[p], 0.f);
    }
}

__global__ void procmem_kernel(const float* __restrict__ enc, const float* __restrict__ Wm) {
    int i = blockIdx.x, b = blockIdx.y;
    __shared__ __align__(16) float se[E_];
    int tid = threadIdx.x;  // 128
    int warp = tid >> 5, lane = tid & 31;
    for (int k = tid; k < E_; k += 128) se[k] = enc[((size_t)b * TENC + i) * E_ + k];
    __syncthreads();
    const float4* se4 = (const float4*)se;
    for (int j = 0; j < 32; j++) {
        int a = warp * 32 + j;
        const float4* w4 = (const float4*)(Wm + (size_t)a * E_);
        float acc = 0.f;
        #pragma unroll
        for (int q = 0; q < 4; q++) {
            float4 w = w4[lane + 32 * q];
            float4 x = se4[lane + 32 * q];
            acc += w.x * x.x + w.y * x.y + w.z * x.z + w.w * x.w;
        }
        acc = warp_sum(acc);
        if (lane == 0) g_pm[((size_t)b * TENC + i) * A_ + a] = acc;
    }
}

// ---------------- launch ----------------
extern "C" void kernel_launch(void* const* d_in, const int* in_sizes, int n_in,
                              void* d_out, int out_size) {
    const float* enc    = (const float*)d_in[0];
    const int*   lens   = (const int*)d_in[1];
    const float* target = (const float*)d_in[2];
    // d_in[3] = teacher_forcing_ratio (==1; fully teacher-forced, unused)
    const float* pW1 = (const float*)d_in[4];
    const float* pb1 = (const float*)d_in[5];
    const float* pW2 = (const float*)d_in[6];
    const float* pb2 = (const float*)d_in[7];
    const float* aWih = (const float*)d_in[8];
    const float* aWhh = (const float*)d_in[9];
    const float* ab   = (const float*)d_in[10];
    const float* gWih = (const float*)d_in[11];
    const float* gWhh = (const float*)d_in[12];
    const float* gb   = (const float*)d_in[13];
    const float* Wq   = (const float*)d_in[14];
    const float* Wm   = (const float*)d_in[15];
    const float* lk   = (const float*)d_in[16];
    const float* Wloc = (const float*)d_in[17];
    const float* v_att = (const float*)d_in[18];
    const float* b_att = (const float*)d_in[19];
    const float* fW = (const float*)d_in[20];
    const float* fb = (const float*)d_in[21];
    const float* sW = (const float*)d_in[22];
    const float* sb = (const float*)d_in[23];

    float* out  = (float*)d_out;
    float* spec  = out;
    float* stop  = out + (size_t)B_ * TDEC * M_;
    float* align = stop + (size_t)B_ * TDEC;

    const int smem_bytes = POOLFL * 4;   // 135168
    static int configured = 0;
    if (!configured) {
        cudaFuncSetAttribute(decoder_kernel, cudaFuncAttributeMaxDynamicSharedMemorySize, smem_bytes);
        configured = 1;
    }

    init_kernel<<<128, 256>>>();
    prenet_kernel<<<B_ * TDEC, 256>>>(target, pW1, pb1, pW2, pb2);
    procmem_kernel<<<dim3(TENC, B_), 128>>>(enc, Wm);

    decoder_kernel<<<NBLK, NTHR, smem_bytes>>>(enc, lens,
                                               aWih, aWhh, ab, gWih, gWhh, gb,
                                               Wq, lk, Wloc, v_att, b_att,
                                               fW, fb, sW, sb,
                                               spec, stop, align);
}